// round 9
// baseline (speedup 1.0000x reference)
#include <cuda_runtime.h>
#include <math.h>

#define NTOK   49
#define CDIM   256
#define HEADS  8
#define HD     32
#define BMAX   2048
#define NN2    2401   // 49*49
#define BMPAD  2404   // NN2 padded so each row is 16B-aligned (2404*4 = 9616)
#define NWMAX  64

// Scratch (allocation-free: __device__ globals)
__device__ float g_qkv[BMAX * NTOK * 768];      // [M][768]  (q|k|v per row)
__device__ float g_att[BMAX * NTOK * CDIM];     // [M][256]
__device__ float g_bias[HEADS * NN2];           // 16*sigmoid(cpb)
__device__ float g_bm[NWMAX * HEADS * BMPAD];   // bias + mask combined (padded rows)

__device__ __forceinline__ float tf32r(float x) {
    unsigned u;
    asm("cvt.rna.tf32.f32 %0, %1;" : "=r"(u) : "f"(x));
    return __uint_as_float(u);
}

__device__ __forceinline__ void mma_tf32(float* c, const unsigned* a, const unsigned* b) {
    asm volatile(
        "mma.sync.aligned.m16n8k8.row.col.f32.tf32.tf32.f32 "
        "{%0,%1,%2,%3}, {%4,%5,%6,%7}, {%8,%9}, {%0,%1,%2,%3};"
        : "+f"(c[0]), "+f"(c[1]), "+f"(c[2]), "+f"(c[3])
        : "r"(a[0]), "r"(a[1]), "r"(a[2]), "r"(a[3]), "r"(b[0]), "r"(b[1]));
}

#define CPA16(dst_u32, src_ptr) \
    asm volatile("cp.async.cg.shared.global [%0], [%1], 16;" :: "r"(dst_u32), "l"(src_ptr))

// ---------------------------------------------------------------------------
// CPB MLP (tiny, one block) -> g_bias[h][ij] = 16*sigmoid(cpb)
// ---------------------------------------------------------------------------
__global__ void cpb_kernel(const float* __restrict__ table,
                           const float* __restrict__ w1,
                           const float* __restrict__ b1,
                           const float* __restrict__ w2,
                           const int*   __restrict__ idx)
{
    __shared__ float t8[169][8];
    const int tid = threadIdx.x;
    for (int e = tid; e < 169 * 8; e += blockDim.x) {
        const int r = e >> 3, hh = e & 7;
        const float t0 = table[r * 2 + 0];
        const float t1 = table[r * 2 + 1];
        float s = 0.f;
        for (int j = 0; j < 512; ++j) {
            float hv = fmaf(t0, w1[j * 2 + 0], fmaf(t1, w1[j * 2 + 1], b1[j]));
            hv = fmaxf(hv, 0.f);
            s = fmaf(hv, w2[hh * 512 + j], s);
        }
        t8[r][hh] = s;
    }
    __syncthreads();
    for (int e = tid; e < HEADS * NN2; e += blockDim.x) {
        const int h = e / NN2, ij = e % NN2;
        const float bv = t8[idx[ij]][h];
        g_bias[e] = 16.f / (1.f + __expf(-bv));
    }
}

// g_bm[wi*H+h][ij] = g_bias[h][ij] + mask[wi][ij]   (rows padded to BMPAD)
__global__ void bm_kernel(const float* __restrict__ mask)
{
    const int wi = blockIdx.x / HEADS, h = blockIdx.x % HEADS;
    const float* mp = mask + (size_t)wi * NN2;
    const float* bp = g_bias + (size_t)h * NN2;
    float* o = g_bm + (size_t)blockIdx.x * BMPAD;
    for (int i = threadIdx.x; i < BMPAD; i += blockDim.x)
        o[i] = (i < NN2) ? (bp[i] + mp[i]) : 0.f;
}

// ---------------------------------------------------------------------------
// 2-stage cp.async tf32 GEMM, convert-once-in-smem, prefetch-before-wait.
// BM=128, BN=128, BK=16, 256 threads. MMA path is pure LDS.
// ---------------------------------------------------------------------------
__device__ __forceinline__ void cvt4_inplace(float* p) {
    float4 v = *(float4*)p;
    v.x = tf32r(v.x); v.y = tf32r(v.y); v.z = tf32r(v.z); v.w = tf32r(v.w);
    *(float4*)p = v;
}

#define GEMM_PIPE(XPTR, WPTR)                                                     \
    __shared__ float As[2][128][20];                                              \
    __shared__ float Bs[2][128][20];                                              \
    const int tid = threadIdx.x;                                                  \
    const int lane = tid & 31, wid = tid >> 5;                                    \
    const int g = lane >> 2, tg = lane & 3;                                       \
    const int wm = (wid & 1) * 64, wn = (wid >> 1) * 32;                          \
    const int m0 = blockIdx.y * 128, n0 = blockIdx.x * 128;                       \
    const int lrow = tid >> 2, lcol = (tid & 3) * 4;                              \
    const float* gA0 = (XPTR) + (size_t)(m0 + lrow) * 256 + lcol;                 \
    const float* gA1 = gA0 + (size_t)64 * 256;                                    \
    const float* gB0 = (WPTR) + (size_t)(n0 + lrow) * 256 + lcol;                 \
    const float* gB1 = gB0 + (size_t)64 * 256;                                    \
    const unsigned sA = (unsigned)__cvta_generic_to_shared(&As[0][lrow][lcol]);   \
    const unsigned sB = (unsigned)__cvta_generic_to_shared(&Bs[0][lrow][lcol]);   \
    const unsigned STG = 128 * 20 * 4;                                            \
    const unsigned HLF = 64 * 20 * 4;                                             \
    float acc[4][4][4];                                                           \
    _Pragma("unroll") for (int i = 0; i < 4; ++i)                                 \
    _Pragma("unroll") for (int j = 0; j < 4; ++j)                                 \
    _Pragma("unroll") for (int r = 0; r < 4; ++r) acc[i][j][r] = 0.f;             \
    CPA16(sA,       gA0);                                                         \
    CPA16(sA + HLF, gA1);                                                         \
    CPA16(sB,       gB0);                                                         \
    CPA16(sB + HLF, gB1);                                                         \
    asm volatile("cp.async.commit_group;");                                       \
    for (int kb = 0; kb < 16; ++kb) {                                             \
        const int s = kb & 1;                                                     \
        if (kb < 15) {                                                            \
            const unsigned so = (unsigned)(s ^ 1) * STG;                          \
            const int kOff = (kb + 1) * 16;                                       \
            CPA16(sA + so,       gA0 + kOff);                                     \
            CPA16(sA + so + HLF, gA1 + kOff);                                     \
            CPA16(sB + so,       gB0 + kOff);                                     \
            CPA16(sB + so + HLF, gB1 + kOff);                                     \
            asm volatile("cp.async.commit_group;");                               \
            asm volatile("cp.async.wait_group 1;");                               \
        } else {                                                                  \
            asm volatile("cp.async.wait_group 0;");                               \
        }                                                                         \
        cvt4_inplace(&As[s][lrow     ][lcol]);                                    \
        cvt4_inplace(&As[s][lrow + 64][lcol]);                                    \
        cvt4_inplace(&Bs[s][lrow     ][lcol]);                                    \
        cvt4_inplace(&Bs[s][lrow + 64][lcol]);                                    \
        __syncthreads();                                                          \
        _Pragma("unroll") for (int ks = 0; ks < 2; ++ks) {                        \
            const int kk = ks * 8;                                                \
            unsigned af[4][4], bf[4][2];                                          \
            _Pragma("unroll") for (int mi = 0; mi < 4; ++mi) {                    \
                const int r = wm + mi * 16 + g;                                   \
                af[mi][0] = __float_as_uint(As[s][r    ][kk + tg]);               \
                af[mi][1] = __float_as_uint(As[s][r + 8][kk + tg]);               \
                af[mi][2] = __float_as_uint(As[s][r    ][kk + tg + 4]);           \
                af[mi][3] = __float_as_uint(As[s][r + 8][kk + tg + 4]);           \
            }                                                                     \
            _Pragma("unroll") for (int ni = 0; ni < 4; ++ni) {                    \
                const int c = wn + ni * 8 + g;                                    \
                bf[ni][0] = __float_as_uint(Bs[s][c][kk + tg]);                   \
                bf[ni][1] = __float_as_uint(Bs[s][c][kk + tg + 4]);               \
            }                                                                     \
            _Pragma("unroll") for (int mi = 0; mi < 4; ++mi)                      \
            _Pragma("unroll") for (int ni = 0; ni < 4; ++ni)                      \
                mma_tf32(acc[mi][ni], af[mi], bf[ni]);                            \
        }                                                                         \
        __syncthreads();                                                          \
    }

__device__ __forceinline__ float qkvb(int o, const float* qb, const float* vb) {
    return (o < 256) ? qb[o] : ((o < 512) ? 0.f : vb[o - 512]);
}

__global__ __launch_bounds__(256) void mma_qkv(const float* __restrict__ X,
                                               const float* __restrict__ W,
                                               const float* __restrict__ qb,
                                               const float* __restrict__ vb)
{
    GEMM_PIPE(X, W)
#pragma unroll
    for (int mi = 0; mi < 4; ++mi) {
        const int mA = m0 + wm + mi * 16 + g;
#pragma unroll
        for (int ni = 0; ni < 4; ++ni) {
            const int o = n0 + wn + ni * 8 + tg * 2;
            const float b0 = qkvb(o, qb, vb), b1 = qkvb(o + 1, qb, vb);
            float2 v0 = make_float2(acc[mi][ni][0] + b0, acc[mi][ni][1] + b1);
            float2 v1 = make_float2(acc[mi][ni][2] + b0, acc[mi][ni][3] + b1);
            *(float2*)&g_qkv[(size_t)mA * 768 + o]       = v0;
            *(float2*)&g_qkv[(size_t)(mA + 8) * 768 + o] = v1;
        }
    }
}

__global__ __launch_bounds__(256) void mma_proj(const float* __restrict__ W,
                                                const float* __restrict__ pb,
                                                float* __restrict__ out)
{
    GEMM_PIPE(g_att, W)
#pragma unroll
    for (int mi = 0; mi < 4; ++mi) {
        const int mA = m0 + wm + mi * 16 + g;
#pragma unroll
        for (int ni = 0; ni < 4; ++ni) {
            const int o = n0 + wn + ni * 8 + tg * 2;
            const float b0 = pb[o], b1 = pb[o + 1];
            float2 v0 = make_float2(acc[mi][ni][0] + b0, acc[mi][ni][1] + b1);
            float2 v1 = make_float2(acc[mi][ni][2] + b0, acc[mi][ni][3] + b1);
            *(float2*)&out[(size_t)mA * 256 + o]       = v0;
            *(float2*)&out[(size_t)(mA + 8) * 256 + o] = v1;
        }
    }
}

// ---------------------------------------------------------------------------
// MMA attention. One block per (b,h), 4 warps. bias+mask tile prefetched
// into smem via cp.async at kernel start (overlaps prologue + QK MMA).
// ---------------------------------------------------------------------------
__global__ __launch_bounds__(128, 4) void attn_mma(const float* __restrict__ logit_scale,
                                                   int nW)
{
    __shared__ float2 qk2[2][64][37];   // [0]=q, [1]=k; (hi, lo)
    __shared__ float  vt[32][68];       // V^T, tf32-rounded
    __shared__ float  bms[BMPAD];       // bias+mask tile
    float* ps = (float*)qk2;            // [64][68] alias

    const int b = blockIdx.x, h = blockIdx.y;
    const int tid = threadIdx.x, w = tid >> 5, lane = tid & 31;
    const int g = lane >> 2, tg = lane & 3;
    const int wm = w * 16;
    const float scale = __expf(fminf(logit_scale[h], 4.605170185988092f)); // ln(100)

    // kick off bias+mask DMA first (601 x 16B = 9616B, row is 16B-aligned)
    {
        const float* bmg = &g_bm[(size_t)((b % nW) * HEADS + h) * BMPAD];
        const unsigned sbm = (unsigned)__cvta_generic_to_shared(bms);
        for (int i = tid; i < BMPAD / 4; i += 128)
            CPA16(sbm + i * 16, bmg + i * 4);
        asm volatile("cp.async.commit_group;");
    }

    // zero token padding
    for (int i = tid; i < 2 * 15 * 37; i += 128) {
        const int s = i / (15 * 37), rem = i % (15 * 37);
        qk2[s][49 + rem / 37][rem % 37] = make_float2(0.f, 0.f);
    }
    for (int i = tid; i < 32 * 15; i += 128)
        vt[i / 15][49 + i % 15] = 0.f;

    // ---- prologue: 2 threads per token, 16 dims each ----
    {
        const int tokr = tid >> 1;
        const bool act = tokr < NTOK;
        const int tok = act ? tokr : NTOK - 1;
        const int hf = tid & 1;
        const float* rp = &g_qkv[(size_t)(b * NTOK + tok) * 768 + h * HD + hf * 16];
        float qv[16], kv[16], vv[16];
#pragma unroll
        for (int i = 0; i < 4; ++i) {
            const float4 q4 = *(const float4*)&rp[i * 4];
            const float4 k4 = *(const float4*)&rp[256 + i * 4];
            const float4 v4 = *(const float4*)&rp[512 + i * 4];
            qv[i*4+0]=q4.x; qv[i*4+1]=q4.y; qv[i*4+2]=q4.z; qv[i*4+3]=q4.w;
            kv[i*4+0]=k4.x; kv[i*4+1]=k4.y; kv[i*4+2]=k4.z; kv[i*4+3]=k4.w;
            vv[i*4+0]=v4.x; vv[i*4+1]=v4.y; vv[i*4+2]=v4.z; vv[i*4+3]=v4.w;
        }
        float sq = 0.f, sk = 0.f;
#pragma unroll
        for (int i = 0; i < 16; ++i) {
            sq = fmaf(qv[i], qv[i], sq);
            sk = fmaf(kv[i], kv[i], sk);
        }
        sq += __shfl_xor_sync(0xffffffffu, sq, 1);
        sk += __shfl_xor_sync(0xffffffffu, sk, 1);
        const float qs = scale / fmaxf(sqrtf(sq), 1e-12f);
        const float ks = 1.f / fmaxf(sqrtf(sk), 1e-12f);
        if (act) {
#pragma unroll
            for (int i = 0; i < 16; ++i) {
                const int d = hf * 16 + i;
                const float qn = qv[i] * qs;
                const float kn = kv[i] * ks;
                const float qhi = tf32r(qn), khi = tf32r(kn);
                qk2[0][tok][d] = make_float2(qhi, tf32r(qn - qhi));
                qk2[1][tok][d] = make_float2(khi, tf32r(kn - khi));
                vt[d][tok] = tf32r(vv[i]);
            }
        }
    }
    __syncthreads();

    // ---- QK^T (3xTF32), warp rows [wm, wm+16), all 64 cols ----
    float acc[8][4];
#pragma unroll
    for (int ni = 0; ni < 8; ++ni)
#pragma unroll
        for (int e = 0; e < 4; ++e) acc[ni][e] = 0.f;

#pragma unroll
    for (int ks = 0; ks < 4; ++ks) {
        const int kk = ks * 8;
        float2 aq[4];
        aq[0] = qk2[0][wm + g    ][kk + tg];
        aq[1] = qk2[0][wm + g + 8][kk + tg];
        aq[2] = qk2[0][wm + g    ][kk + tg + 4];
        aq[3] = qk2[0][wm + g + 8][kk + tg + 4];
        unsigned ah[4], al[4];
#pragma unroll
        for (int e = 0; e < 4; ++e) {
            ah[e] = __float_as_uint(aq[e].x);
            al[e] = __float_as_uint(aq[e].y);
        }
#pragma unroll
        for (int ni = 0; ni < 8; ++ni) {
            const int c = ni * 8 + g;
            const float2 b0 = qk2[1][c][kk + tg];
            const float2 b1 = qk2[1][c][kk + tg + 4];
            unsigned bh[2], bl[2];
            bh[0] = __float_as_uint(b0.x); bh[1] = __float_as_uint(b1.x);
            bl[0] = __float_as_uint(b0.y); bl[1] = __float_as_uint(b1.y);
            mma_tf32(acc[ni], ah, bh);
            mma_tf32(acc[ni], ah, bl);
            mma_tf32(acc[ni], al, bh);
        }
    }
    asm volatile("cp.async.wait_group 0;");   // bms resident
    __syncthreads();   // all warps done reading qk2; ps may overwrite it

    // ---- bias+mask add from smem, pad masking ----
    const int r0 = wm + g, r1 = wm + g + 8;
#pragma unroll
    for (int ni = 0; ni < 8; ++ni) {
        const int c0 = ni * 8 + tg * 2, c1 = c0 + 1;
        if (c0 < 49) { if (r0 < 49) acc[ni][0] += bms[r0 * 49 + c0];
                       if (r1 < 49) acc[ni][2] += bms[r1 * 49 + c0]; }
        else { acc[ni][0] = -1e30f; acc[ni][2] = -1e30f; }
        if (c1 < 49) { if (r0 < 49) acc[ni][1] += bms[r0 * 49 + c1];
                       if (r1 < 49) acc[ni][3] += bms[r1 * 49 + c1]; }
        else { acc[ni][1] = -1e30f; acc[ni][3] = -1e30f; }
    }

    // ---- softmax over 64 cols of rows r0, r1 ----
    float m0 = -1e30f, m1 = -1e30f;
#pragma unroll
    for (int ni = 0; ni < 8; ++ni) {
        m0 = fmaxf(m0, fmaxf(acc[ni][0], acc[ni][1]));
        m1 = fmaxf(m1, fmaxf(acc[ni][2], acc[ni][3]));
    }
    m0 = fmaxf(m0, __shfl_xor_sync(0xffffffffu, m0, 1));
    m0 = fmaxf(m0, __shfl_xor_sync(0xffffffffu, m0, 2));
    m1 = fmaxf(m1, __shfl_xor_sync(0xffffffffu, m1, 1));
    m1 = fmaxf(m1, __shfl_xor_sync(0xffffffffu, m1, 2));
    float s0 = 0.f, s1 = 0.f;
#pragma unroll
    for (int ni = 0; ni < 8; ++ni) {
        acc[ni][0] = __expf(acc[ni][0] - m0); s0 += acc[ni][0];
        acc[ni][1] = __expf(acc[ni][1] - m0); s0 += acc[ni][1];
        acc[ni][2] = __expf(acc[ni][2] - m1); s1 += acc[ni][2];
        acc[ni][3] = __expf(acc[ni][3] - m1); s1 += acc[ni][3];
    }
    s0 += __shfl_xor_sync(0xffffffffu, s0, 1);
    s0 += __shfl_xor_sync(0xffffffffu, s0, 2);
    s1 += __shfl_xor_sync(0xffffffffu, s1, 1);
    s1 += __shfl_xor_sync(0xffffffffu, s1, 2);
    const float i0 = 1.f / s0, i1 = 1.f / s1;
#pragma unroll
    for (int ni = 0; ni < 8; ++ni) {
        const int c0 = ni * 8 + tg * 2;
        ps[r0 * 68 + c0]     = tf32r(acc[ni][0] * i0);
        ps[r0 * 68 + c0 + 1] = tf32r(acc[ni][1] * i0);
        ps[r1 * 68 + c0]     = tf32r(acc[ni][2] * i1);
        ps[r1 * 68 + c0 + 1] = tf32r(acc[ni][3] * i1);
    }
    __syncwarp();   // ps rows [wm,wm+16) written & read only by this warp

    // ---- AV: out[16 x 32] = P[16 x 64] @ V[64 x 32] ----
    float oacc[4][4];
#pragma unroll
    for (int ni = 0; ni < 4; ++ni)
#pragma unroll
        for (int e = 0; e < 4; ++e) oacc[ni][e] = 0.f;

#pragma unroll
    for (int ks = 0; ks < 8; ++ks) {
        const int kk = ks * 8;
        unsigned a[4];
        a[0] = __float_as_uint(ps[(wm + g    ) * 68 + kk + tg]);
        a[1] = __float_as_uint(ps[(wm + g + 8) * 68 + kk + tg]);
        a[2] = __float_as_uint(ps[(wm + g    ) * 68 + kk + tg + 4]);
        a[3] = __float_as_uint(ps[(wm + g + 8) * 68 + kk + tg + 4]);
#pragma unroll
        for (int ni = 0; ni < 4; ++ni) {
            const int c = ni * 8 + g;
            unsigned bb[2];
            bb[0] = __float_as_uint(vt[c][kk + tg]);
            bb[1] = __float_as_uint(vt[c][kk + tg + 4]);
            mma_tf32(oacc[ni], a, bb);
        }
    }

    if (r0 < 49) {
        float* op = &g_att[(size_t)(b * NTOK + r0) * CDIM + h * HD];
#pragma unroll
        for (int ni = 0; ni < 4; ++ni)
            *(float2*)&op[ni * 8 + tg * 2] = make_float2(oacc[ni][0], oacc[ni][1]);
    }
    if (r1 < 49) {
        float* op = &g_att[(size_t)(b * NTOK + r1) * CDIM + h * HD];
#pragma unroll
        for (int ni = 0; ni < 4; ++ni)
            *(float2*)&op[ni * 8 + tg * 2] = make_float2(oacc[ni][2], oacc[ni][3]);
    }
}

// ---------------------------------------------------------------------------
extern "C" void kernel_launch(void* const* d_in, const int* in_sizes, int n_in,
                              void* d_out, int out_size)
{
    const float* x        = (const float*)d_in[0];
    const float* mask     = (const float*)d_in[1];
    const float* qkv_w    = (const float*)d_in[2];
    const float* q_bias   = (const float*)d_in[3];
    const float* v_bias   = (const float*)d_in[4];
    const float* logit_sc = (const float*)d_in[5];
    const float* cpb_w1   = (const float*)d_in[6];
    const float* cpb_b1   = (const float*)d_in[7];
    const float* cpb_w2   = (const float*)d_in[8];
    const float* proj_w   = (const float*)d_in[9];
    const float* proj_b   = (const float*)d_in[10];
    const float* table    = (const float*)d_in[11];
    const int*   rel_idx  = (const int*)d_in[12];

    const int B  = in_sizes[0] / (NTOK * CDIM);      // 2048
    const int nW = in_sizes[1] / NN2;                // 64
    const int M  = B * NTOK;                         // 100352

    mma_qkv<<<dim3(768 / 128, M / 128), 256>>>(x, qkv_w, q_bias, v_bias);
    cpb_kernel<<<1, 256>>>(table, cpb_w1, cpb_b1, cpb_w2, rel_idx);
    bm_kernel<<<nW * HEADS, 256>>>(mask);
    attn_mma<<<dim3(B, HEADS), 128>>>(logit_sc, nW);
    mma_proj<<<dim3(256 / 128, M / 128), 256>>>(proj_w, proj_b, (float*)d_out);
}

// round 10
// speedup vs baseline: 1.1502x; 1.1502x over previous
#include <cuda_runtime.h>
#include <math.h>

#define NTOK   49
#define CDIM   256
#define HEADS  8
#define HD     32
#define BMAX   2048
#define NN2    2401   // 49*49
#define BMPAD  2404   // NN2 padded so each row is 16B-aligned
#define NWMAX  64
#define MMAX   (BMAX * NTOK)

// Scratch (allocation-free: __device__ globals)
__device__ float g_qkv[MMAX * 768];             // [M][768]  (q|k|v per row)
__device__ float g_att[MMAX * CDIM];            // [M][256]  (tf32-rounded by attn)
__device__ float g_xr[MMAX * CDIM];             // tf32-rounded x
__device__ float g_wqr[768 * 256];              // tf32-rounded qkv_w
__device__ float g_wpr[256 * 256];              // tf32-rounded proj_w
__device__ float g_bias[HEADS * NN2];           // 16*sigmoid(cpb)
__device__ float g_bm[NWMAX * HEADS * BMPAD];   // bias + mask combined (padded rows)

__device__ __forceinline__ float tf32r(float x) {
    unsigned u;
    asm("cvt.rna.tf32.f32 %0, %1;" : "=r"(u) : "f"(x));
    return __uint_as_float(u);
}

__device__ __forceinline__ void mma_tf32(float* c, const unsigned* a, const unsigned* b) {
    asm volatile(
        "mma.sync.aligned.m16n8k8.row.col.f32.tf32.tf32.f32 "
        "{%0,%1,%2,%3}, {%4,%5,%6,%7}, {%8,%9}, {%0,%1,%2,%3};"
        : "+f"(c[0]), "+f"(c[1]), "+f"(c[2]), "+f"(c[3])
        : "r"(a[0]), "r"(a[1]), "r"(a[2]), "r"(a[3]), "r"(b[0]), "r"(b[1]));
}

#define CPA16(dst_u32, src_ptr) \
    asm volatile("cp.async.cg.shared.global [%0], [%1], 16;" :: "r"(dst_u32), "l"(src_ptr))

// ---------------------------------------------------------------------------
// tf32 pre-round passes
// ---------------------------------------------------------------------------
__global__ void round_x_kernel(const float* __restrict__ x, int n4)
{
    const int stride = gridDim.x * blockDim.x;
    for (int i = blockIdx.x * blockDim.x + threadIdx.x; i < n4; i += stride) {
        float4 v = ((const float4*)x)[i];
        v.x = tf32r(v.x); v.y = tf32r(v.y); v.z = tf32r(v.z); v.w = tf32r(v.w);
        ((float4*)g_xr)[i] = v;
    }
}

__global__ void round_w_kernel(const float* __restrict__ qkv_w,
                               const float* __restrict__ proj_w)
{
    const int stride = gridDim.x * blockDim.x;
    const int nq = 768 * 256 / 4, np = 256 * 256 / 4;
    for (int i = blockIdx.x * blockDim.x + threadIdx.x; i < nq + np; i += stride) {
        if (i < nq) {
            float4 v = ((const float4*)qkv_w)[i];
            v.x = tf32r(v.x); v.y = tf32r(v.y); v.z = tf32r(v.z); v.w = tf32r(v.w);
            ((float4*)g_wqr)[i] = v;
        } else {
            float4 v = ((const float4*)proj_w)[i - nq];
            v.x = tf32r(v.x); v.y = tf32r(v.y); v.z = tf32r(v.z); v.w = tf32r(v.w);
            ((float4*)g_wpr)[i - nq] = v;
        }
    }
}

// ---------------------------------------------------------------------------
// CPB MLP (tiny, one block) -> g_bias[h][ij] = 16*sigmoid(cpb)
// ---------------------------------------------------------------------------
__global__ void cpb_kernel(const float* __restrict__ table,
                           const float* __restrict__ w1,
                           const float* __restrict__ b1,
                           const float* __restrict__ w2,
                           const int*   __restrict__ idx)
{
    __shared__ float t8[169][8];
    const int tid = threadIdx.x;
    for (int e = tid; e < 169 * 8; e += blockDim.x) {
        const int r = e >> 3, hh = e & 7;
        const float t0 = table[r * 2 + 0];
        const float t1 = table[r * 2 + 1];
        float s = 0.f;
        for (int j = 0; j < 512; ++j) {
            float hv = fmaf(t0, w1[j * 2 + 0], fmaf(t1, w1[j * 2 + 1], b1[j]));
            hv = fmaxf(hv, 0.f);
            s = fmaf(hv, w2[hh * 512 + j], s);
        }
        t8[r][hh] = s;
    }
    __syncthreads();
    for (int e = tid; e < HEADS * NN2; e += blockDim.x) {
        const int h = e / NN2, ij = e % NN2;
        const float bv = t8[idx[ij]][h];
        g_bias[e] = 16.f / (1.f + __expf(-bv));
    }
}

// g_bm[wi*H+h][ij] = g_bias[h][ij] + mask[wi][ij]   (rows padded to BMPAD)
__global__ void bm_kernel(const float* __restrict__ mask)
{
    const int wi = blockIdx.x / HEADS, h = blockIdx.x % HEADS;
    const float* mp = mask + (size_t)wi * NN2;
    const float* bp = g_bias + (size_t)h * NN2;
    float* o = g_bm + (size_t)blockIdx.x * BMPAD;
    for (int i = threadIdx.x; i < BMPAD; i += blockDim.x)
        o[i] = (i < NN2) ? (bp[i] + mp[i]) : 0.f;
}

// ---------------------------------------------------------------------------
// 2-stage cp.async tf32 GEMM (round-6 pipeline, operands pre-rounded in gmem
// so fragment loads are plain LDS). BM=128, BN=128, BK=16, 256 threads.
// ---------------------------------------------------------------------------
#define GEMM_PIPE(XPTR, WPTR)                                                     \
    __shared__ float As[2][128][20];                                              \
    __shared__ float Bs[2][128][20];                                              \
    const int tid = threadIdx.x;                                                  \
    const int lane = tid & 31, wid = tid >> 5;                                    \
    const int g = lane >> 2, tg = lane & 3;                                       \
    const int wm = (wid & 1) * 64, wn = (wid >> 1) * 32;                          \
    const int m0 = blockIdx.y * 128, n0 = blockIdx.x * 128;                       \
    const int lrow = tid >> 2, lcol = (tid & 3) * 4;                              \
    const float* gA0 = (XPTR) + (size_t)(m0 + lrow) * 256 + lcol;                 \
    const float* gA1 = gA0 + (size_t)64 * 256;                                    \
    const float* gB0 = (WPTR) + (size_t)(n0 + lrow) * 256 + lcol;                 \
    const float* gB1 = gB0 + (size_t)64 * 256;                                    \
    const unsigned sA = (unsigned)__cvta_generic_to_shared(&As[0][lrow][lcol]);   \
    const unsigned sB = (unsigned)__cvta_generic_to_shared(&Bs[0][lrow][lcol]);   \
    const unsigned STG = 128 * 20 * 4;                                            \
    const unsigned HLF = 64 * 20 * 4;                                             \
    float acc[4][4][4];                                                           \
    _Pragma("unroll") for (int i = 0; i < 4; ++i)                                 \
    _Pragma("unroll") for (int j = 0; j < 4; ++j)                                 \
    _Pragma("unroll") for (int r = 0; r < 4; ++r) acc[i][j][r] = 0.f;             \
    CPA16(sA,       gA0);                                                         \
    CPA16(sA + HLF, gA1);                                                         \
    CPA16(sB,       gB0);                                                         \
    CPA16(sB + HLF, gB1);                                                         \
    asm volatile("cp.async.commit_group;");                                       \
    for (int kb = 0; kb < 16; ++kb) {                                             \
        if (kb < 15) {                                                            \
            const int sNext = (kb + 1) & 1;                                       \
            const int kOff = (kb + 1) * 16;                                       \
            CPA16(sA + sNext * STG,       gA0 + kOff);                            \
            CPA16(sA + sNext * STG + HLF, gA1 + kOff);                            \
            CPA16(sB + sNext * STG,       gB0 + kOff);                            \
            CPA16(sB + sNext * STG + HLF, gB1 + kOff);                            \
            asm volatile("cp.async.commit_group;");                               \
            asm volatile("cp.async.wait_group 1;");                               \
        } else {                                                                  \
            asm volatile("cp.async.wait_group 0;");                               \
        }                                                                         \
        __syncthreads();                                                          \
        const int s = kb & 1;                                                     \
        _Pragma("unroll") for (int ks = 0; ks < 2; ++ks) {                        \
            const int kk = ks * 8;                                                \
            unsigned af[4][4], bf[4][2];                                          \
            _Pragma("unroll") for (int mi = 0; mi < 4; ++mi) {                    \
                const int r = wm + mi * 16 + g;                                   \
                af[mi][0] = __float_as_uint(As[s][r    ][kk + tg]);               \
                af[mi][1] = __float_as_uint(As[s][r + 8][kk + tg]);               \
                af[mi][2] = __float_as_uint(As[s][r    ][kk + tg + 4]);           \
                af[mi][3] = __float_as_uint(As[s][r + 8][kk + tg + 4]);           \
            }                                                                     \
            _Pragma("unroll") for (int ni = 0; ni < 4; ++ni) {                    \
                const int c = wn + ni * 8 + g;                                    \
                bf[ni][0] = __float_as_uint(Bs[s][c][kk + tg]);                   \
                bf[ni][1] = __float_as_uint(Bs[s][c][kk + tg + 4]);               \
            }                                                                     \
            _Pragma("unroll") for (int mi = 0; mi < 4; ++mi)                      \
            _Pragma("unroll") for (int ni = 0; ni < 4; ++ni)                      \
                mma_tf32(acc[mi][ni], af[mi], bf[ni]);                            \
        }                                                                         \
        __syncthreads();                                                          \
    }

__device__ __forceinline__ float qkvb(int o, const float* qb, const float* vb) {
    return (o < 256) ? qb[o] : ((o < 512) ? 0.f : vb[o - 512]);
}

__global__ __launch_bounds__(256) void mma_qkv(const float* __restrict__ qb,
                                               const float* __restrict__ vb)
{
    GEMM_PIPE(g_xr, g_wqr)
#pragma unroll
    for (int mi = 0; mi < 4; ++mi) {
        const int mA = m0 + wm + mi * 16 + g;
#pragma unroll
        for (int ni = 0; ni < 4; ++ni) {
            const int o = n0 + wn + ni * 8 + tg * 2;
            const float b0 = qkvb(o, qb, vb), b1 = qkvb(o + 1, qb, vb);
            float2 v0 = make_float2(acc[mi][ni][0] + b0, acc[mi][ni][1] + b1);
            float2 v1 = make_float2(acc[mi][ni][2] + b0, acc[mi][ni][3] + b1);
            *(float2*)&g_qkv[(size_t)mA * 768 + o]       = v0;
            *(float2*)&g_qkv[(size_t)(mA + 8) * 768 + o] = v1;
        }
    }
}

__global__ __launch_bounds__(256) void mma_proj(const float* __restrict__ pb,
                                                float* __restrict__ out)
{
    GEMM_PIPE(g_att, g_wpr)
#pragma unroll
    for (int mi = 0; mi < 4; ++mi) {
        const int mA = m0 + wm + mi * 16 + g;
#pragma unroll
        for (int ni = 0; ni < 4; ++ni) {
            const int o = n0 + wn + ni * 8 + tg * 2;
            const float b0 = pb[o], b1 = pb[o + 1];
            float2 v0 = make_float2(acc[mi][ni][0] + b0, acc[mi][ni][1] + b1);
            float2 v1 = make_float2(acc[mi][ni][2] + b0, acc[mi][ni][3] + b1);
            *(float2*)&out[(size_t)mA * 256 + o]       = v0;
            *(float2*)&out[(size_t)(mA + 8) * 256 + o] = v1;
        }
    }
}

// ---------------------------------------------------------------------------
// MMA attention (round-9 proven, 240us). One block per (b,h), 4 warps.
// bias+mask prefetched via cp.async; epilogue stores tf32-rounded output
// (numerically identical to proj's former per-fragment rounding).
// ---------------------------------------------------------------------------
__global__ __launch_bounds__(128, 4) void attn_mma(const float* __restrict__ logit_scale,
                                                   int nW)
{
    __shared__ float2 qk2[2][64][37];   // [0]=q, [1]=k; (hi, lo)
    __shared__ float  vt[32][68];       // V^T, tf32-rounded
    __shared__ float  bms[BMPAD];       // bias+mask tile
    float* ps = (float*)qk2;            // [64][68] alias

    const int b = blockIdx.x, h = blockIdx.y;
    const int tid = threadIdx.x, w = tid >> 5, lane = tid & 31;
    const int g = lane >> 2, tg = lane & 3;
    const int wm = w * 16;
    const float scale = __expf(fminf(logit_scale[h], 4.605170185988092f)); // ln(100)

    // kick off bias+mask DMA first
    {
        const float* bmg = &g_bm[(size_t)((b % nW) * HEADS + h) * BMPAD];
        const unsigned sbm = (unsigned)__cvta_generic_to_shared(bms);
        for (int i = tid; i < BMPAD / 4; i += 128)
            CPA16(sbm + i * 16, bmg + i * 4);
        asm volatile("cp.async.commit_group;");
    }

    // zero token padding
    for (int i = tid; i < 2 * 15 * 37; i += 128) {
        const int s = i / (15 * 37), rem = i % (15 * 37);
        qk2[s][49 + rem / 37][rem % 37] = make_float2(0.f, 0.f);
    }
    for (int i = tid; i < 32 * 15; i += 128)
        vt[i / 15][49 + i % 15] = 0.f;

    // ---- prologue: 2 threads per token, 16 dims each ----
    {
        const int tokr = tid >> 1;
        const bool act = tokr < NTOK;
        const int tok = act ? tokr : NTOK - 1;
        const int hf = tid & 1;
        const float* rp = &g_qkv[(size_t)(b * NTOK + tok) * 768 + h * HD + hf * 16];
        float qv[16], kv[16], vv[16];
#pragma unroll
        for (int i = 0; i < 4; ++i) {
            const float4 q4 = *(const float4*)&rp[i * 4];
            const float4 k4 = *(const float4*)&rp[256 + i * 4];
            const float4 v4 = *(const float4*)&rp[512 + i * 4];
            qv[i*4+0]=q4.x; qv[i*4+1]=q4.y; qv[i*4+2]=q4.z; qv[i*4+3]=q4.w;
            kv[i*4+0]=k4.x; kv[i*4+1]=k4.y; kv[i*4+2]=k4.z; kv[i*4+3]=k4.w;
            vv[i*4+0]=v4.x; vv[i*4+1]=v4.y; vv[i*4+2]=v4.z; vv[i*4+3]=v4.w;
        }
        float sq = 0.f, sk = 0.f;
#pragma unroll
        for (int i = 0; i < 16; ++i) {
            sq = fmaf(qv[i], qv[i], sq);
            sk = fmaf(kv[i], kv[i], sk);
        }
        sq += __shfl_xor_sync(0xffffffffu, sq, 1);
        sk += __shfl_xor_sync(0xffffffffu, sk, 1);
        const float qs = scale / fmaxf(sqrtf(sq), 1e-12f);
        const float ks = 1.f / fmaxf(sqrtf(sk), 1e-12f);
        if (act) {
#pragma unroll
            for (int i = 0; i < 16; ++i) {
                const int d = hf * 16 + i;
                const float qn = qv[i] * qs;
                const float kn = kv[i] * ks;
                const float qhi = tf32r(qn), khi = tf32r(kn);
                qk2[0][tok][d] = make_float2(qhi, tf32r(qn - qhi));
                qk2[1][tok][d] = make_float2(khi, tf32r(kn - khi));
                vt[d][tok] = tf32r(vv[i]);
            }
        }
    }
    __syncthreads();

    // ---- QK^T (3xTF32), warp rows [wm, wm+16), all 64 cols ----
    float acc[8][4];
#pragma unroll
    for (int ni = 0; ni < 8; ++ni)
#pragma unroll
        for (int e = 0; e < 4; ++e) acc[ni][e] = 0.f;

#pragma unroll
    for (int ks = 0; ks < 4; ++ks) {
        const int kk = ks * 8;
        float2 aq[4];
        aq[0] = qk2[0][wm + g    ][kk + tg];
        aq[1] = qk2[0][wm + g + 8][kk + tg];
        aq[2] = qk2[0][wm + g    ][kk + tg + 4];
        aq[3] = qk2[0][wm + g + 8][kk + tg + 4];
        unsigned ah[4], al[4];
#pragma unroll
        for (int e = 0; e < 4; ++e) {
            ah[e] = __float_as_uint(aq[e].x);
            al[e] = __float_as_uint(aq[e].y);
        }
#pragma unroll
        for (int ni = 0; ni < 8; ++ni) {
            const int c = ni * 8 + g;
            const float2 b0 = qk2[1][c][kk + tg];
            const float2 b1 = qk2[1][c][kk + tg + 4];
            unsigned bh[2], bl[2];
            bh[0] = __float_as_uint(b0.x); bh[1] = __float_as_uint(b1.x);
            bl[0] = __float_as_uint(b0.y); bl[1] = __float_as_uint(b1.y);
            mma_tf32(acc[ni], ah, bh);
            mma_tf32(acc[ni], ah, bl);
            mma_tf32(acc[ni], al, bh);
        }
    }
    asm volatile("cp.async.wait_group 0;");   // bms resident
    __syncthreads();   // all warps done reading qk2; ps may overwrite it

    // ---- bias+mask add from smem, pad masking ----
    const int r0 = wm + g, r1 = wm + g + 8;
#pragma unroll
    for (int ni = 0; ni < 8; ++ni) {
        const int c0 = ni * 8 + tg * 2, c1 = c0 + 1;
        if (c0 < 49) { if (r0 < 49) acc[ni][0] += bms[r0 * 49 + c0];
                       if (r1 < 49) acc[ni][2] += bms[r1 * 49 + c0]; }
        else { acc[ni][0] = -1e30f; acc[ni][2] = -1e30f; }
        if (c1 < 49) { if (r0 < 49) acc[ni][1] += bms[r0 * 49 + c1];
                       if (r1 < 49) acc[ni][3] += bms[r1 * 49 + c1]; }
        else { acc[ni][1] = -1e30f; acc[ni][3] = -1e30f; }
    }

    // ---- softmax over 64 cols of rows r0, r1 ----
    float m0 = -1e30f, m1 = -1e30f;
#pragma unroll
    for (int ni = 0; ni < 8; ++ni) {
        m0 = fmaxf(m0, fmaxf(acc[ni][0], acc[ni][1]));
        m1 = fmaxf(m1, fmaxf(acc[ni][2], acc[ni][3]));
    }
    m0 = fmaxf(m0, __shfl_xor_sync(0xffffffffu, m0, 1));
    m0 = fmaxf(m0, __shfl_xor_sync(0xffffffffu, m0, 2));
    m1 = fmaxf(m1, __shfl_xor_sync(0xffffffffu, m1, 1));
    m1 = fmaxf(m1, __shfl_xor_sync(0xffffffffu, m1, 2));
    float s0 = 0.f, s1 = 0.f;
#pragma unroll
    for (int ni = 0; ni < 8; ++ni) {
        acc[ni][0] = __expf(acc[ni][0] - m0); s0 += acc[ni][0];
        acc[ni][1] = __expf(acc[ni][1] - m0); s0 += acc[ni][1];
        acc[ni][2] = __expf(acc[ni][2] - m1); s1 += acc[ni][2];
        acc[ni][3] = __expf(acc[ni][3] - m1); s1 += acc[ni][3];
    }
    s0 += __shfl_xor_sync(0xffffffffu, s0, 1);
    s0 += __shfl_xor_sync(0xffffffffu, s0, 2);
    s1 += __shfl_xor_sync(0xffffffffu, s1, 1);
    s1 += __shfl_xor_sync(0xffffffffu, s1, 2);
    const float i0 = 1.f / s0, i1 = 1.f / s1;
#pragma unroll
    for (int ni = 0; ni < 8; ++ni) {
        const int c0 = ni * 8 + tg * 2;
        ps[r0 * 68 + c0]     = tf32r(acc[ni][0] * i0);
        ps[r0 * 68 + c0 + 1] = tf32r(acc[ni][1] * i0);
        ps[r1 * 68 + c0]     = tf32r(acc[ni][2] * i1);
        ps[r1 * 68 + c0 + 1] = tf32r(acc[ni][3] * i1);
    }
    __syncwarp();   // ps rows [wm,wm+16) written & read only by this warp

    // ---- AV: out[16 x 32] = P[16 x 64] @ V[64 x 32] ----
    float oacc[4][4];
#pragma unroll
    for (int ni = 0; ni < 4; ++ni)
#pragma unroll
        for (int e = 0; e < 4; ++e) oacc[ni][e] = 0.f;

#pragma unroll
    for (int ks = 0; ks < 8; ++ks) {
        const int kk = ks * 8;
        unsigned a[4];
        a[0] = __float_as_uint(ps[(wm + g    ) * 68 + kk + tg]);
        a[1] = __float_as_uint(ps[(wm + g + 8) * 68 + kk + tg]);
        a[2] = __float_as_uint(ps[(wm + g    ) * 68 + kk + tg + 4]);
        a[3] = __float_as_uint(ps[(wm + g + 8) * 68 + kk + tg + 4]);
#pragma unroll
        for (int ni = 0; ni < 4; ++ni) {
            const int c = ni * 8 + g;
            unsigned bb[2];
            bb[0] = __float_as_uint(vt[c][kk + tg]);
            bb[1] = __float_as_uint(vt[c][kk + tg + 4]);
            mma_tf32(oacc[ni], a, bb);
        }
    }

    // tf32-rounded store (identical numerics to proj rounding it on load)
    if (r0 < 49) {
        float* op = &g_att[(size_t)(b * NTOK + r0) * CDIM + h * HD];
#pragma unroll
        for (int ni = 0; ni < 4; ++ni)
            *(float2*)&op[ni * 8 + tg * 2] =
                make_float2(tf32r(oacc[ni][0]), tf32r(oacc[ni][1]));
    }
    if (r1 < 49) {
        float* op = &g_att[(size_t)(b * NTOK + r1) * CDIM + h * HD];
#pragma unroll
        for (int ni = 0; ni < 4; ++ni)
            *(float2*)&op[ni * 8 + tg * 2] =
                make_float2(tf32r(oacc[ni][2]), tf32r(oacc[ni][3]));
    }
}

// ---------------------------------------------------------------------------
extern "C" void kernel_launch(void* const* d_in, const int* in_sizes, int n_in,
                              void* d_out, int out_size)
{
    const float* x        = (const float*)d_in[0];
    const float* mask     = (const float*)d_in[1];
    const float* qkv_w    = (const float*)d_in[2];
    const float* q_bias   = (const float*)d_in[3];
    const float* v_bias   = (const float*)d_in[4];
    const float* logit_sc = (const float*)d_in[5];
    const float* cpb_w1   = (const float*)d_in[6];
    const float* cpb_b1   = (const float*)d_in[7];
    const float* cpb_w2   = (const float*)d_in[8];
    const float* proj_w   = (const float*)d_in[9];
    const float* proj_b   = (const float*)d_in[10];
    const float* table    = (const float*)d_in[11];
    const int*   rel_idx  = (const int*)d_in[12];

    const int B  = in_sizes[0] / (NTOK * CDIM);      // 2048
    const int nW = in_sizes[1] / NN2;                // 64
    const int M  = B * NTOK;                         // 100352

    round_x_kernel<<<2048, 256>>>(x, M * CDIM / 4);
    round_w_kernel<<<256, 256>>>(qkv_w, proj_w);
    mma_qkv<<<dim3(768 / 128, M / 128), 256>>>(q_bias, v_bias);
    cpb_kernel<<<1, 256>>>(table, cpb_w1, cpb_b1, cpb_w2, rel_idx);
    bm_kernel<<<nW * HEADS, 256>>>(mask);
    attn_mma<<<dim3(B, HEADS), 128>>>(logit_sc, nW);
    mma_proj<<<dim3(256 / 128, M / 128), 256>>>(proj_b, (float*)d_out);
}

// round 11
// speedup vs baseline: 1.3949x; 1.2127x over previous
#include <cuda_runtime.h>
#include <math.h>

#define NTOK   49
#define CDIM   256
#define HEADS  8
#define HD     32
#define BMAX   2048
#define NN2    2401   // 49*49
#define BMPAD  2404   // NN2 padded so each row is 16B-aligned
#define NWMAX  64
#define MMAX   (BMAX * NTOK)

// Scratch (allocation-free: __device__ globals)
__device__ float g_qkv[MMAX * 768];             // [M][768]  (q|k|v per row)
__device__ float g_att[MMAX * CDIM];            // [M][256]  (tf32-rounded by attn)
__device__ float g_xr[MMAX * CDIM];             // tf32-rounded x
__device__ float g_wqr[768 * 256];              // tf32-rounded qkv_w
__device__ float g_wpr[256 * 256];              // tf32-rounded proj_w
__device__ float g_t8[169 * 8];                 // raw CPB MLP output [r][h]
__device__ float g_bm[NWMAX * HEADS * BMPAD];   // 16*sigmoid(bias) + mask

__device__ __forceinline__ float tf32r(float x) {
    unsigned u;
    asm("cvt.rna.tf32.f32 %0, %1;" : "=r"(u) : "f"(x));
    return __uint_as_float(u);
}

__device__ __forceinline__ void mma_tf32(float* c, const unsigned* a, const unsigned* b) {
    asm volatile(
        "mma.sync.aligned.m16n8k8.row.col.f32.tf32.tf32.f32 "
        "{%0,%1,%2,%3}, {%4,%5,%6,%7}, {%8,%9}, {%0,%1,%2,%3};"
        : "+f"(c[0]), "+f"(c[1]), "+f"(c[2]), "+f"(c[3])
        : "r"(a[0]), "r"(a[1]), "r"(a[2]), "r"(a[3]), "r"(b[0]), "r"(b[1]));
}

#define CPA16(dst_u32, src_ptr) \
    asm volatile("cp.async.cg.shared.global [%0], [%1], 16;" :: "r"(dst_u32), "l"(src_ptr))

// ---------------------------------------------------------------------------
// tf32 pre-round passes
// ---------------------------------------------------------------------------
__global__ void round_x_kernel(const float* __restrict__ x, int n4)
{
    const int stride = gridDim.x * blockDim.x;
    for (int i = blockIdx.x * blockDim.x + threadIdx.x; i < n4; i += stride) {
        float4 v = ((const float4*)x)[i];
        v.x = tf32r(v.x); v.y = tf32r(v.y); v.z = tf32r(v.z); v.w = tf32r(v.w);
        ((float4*)g_xr)[i] = v;
    }
}

__global__ void round_w_kernel(const float* __restrict__ qkv_w,
                               const float* __restrict__ proj_w)
{
    const int stride = gridDim.x * blockDim.x;
    const int nq = 768 * 256 / 4, np = 256 * 256 / 4;
    for (int i = blockIdx.x * blockDim.x + threadIdx.x; i < nq + np; i += stride) {
        if (i < nq) {
            float4 v = ((const float4*)qkv_w)[i];
            v.x = tf32r(v.x); v.y = tf32r(v.y); v.z = tf32r(v.z); v.w = tf32r(v.w);
            ((float4*)g_wqr)[i] = v;
        } else {
            float4 v = ((const float4*)proj_w)[i - nq];
            v.x = tf32r(v.x); v.y = tf32r(v.y); v.z = tf32r(v.z); v.w = tf32r(v.w);
            ((float4*)g_wpr)[i - nq] = v;
        }
    }
}

// ---------------------------------------------------------------------------
// CPB MLP, parallel: one warp per (row r, head hh). 169 blocks x 8 warps.
// Each lane sums 16 of the 512 hidden units; shfl reduce.
// ---------------------------------------------------------------------------
__global__ void cpb_kernel(const float* __restrict__ table,
                           const float* __restrict__ w1,
                           const float* __restrict__ b1,
                           const float* __restrict__ w2)
{
    const int r = blockIdx.x;                 // 0..168
    const int hh = threadIdx.x >> 5;          // 0..7
    const int lane = threadIdx.x & 31;
    const float t0 = table[r * 2 + 0];
    const float t1 = table[r * 2 + 1];
    float s = 0.f;
#pragma unroll
    for (int it = 0; it < 16; ++it) {
        const int j = lane + it * 32;
        float hv = fmaf(t0, w1[j * 2 + 0], fmaf(t1, w1[j * 2 + 1], b1[j]));
        hv = fmaxf(hv, 0.f);
        s = fmaf(hv, w2[hh * 512 + j], s);
    }
#pragma unroll
    for (int o = 16; o > 0; o >>= 1)
        s += __shfl_xor_sync(0xffffffffu, s, o);
    if (lane == 0) g_t8[r * 8 + hh] = s;
}

// g_bm[wi*H+h][ij] = 16*sigmoid(g_t8[idx[ij]][h]) + mask[wi][ij]
__global__ void bm_kernel(const float* __restrict__ mask,
                          const int* __restrict__ idx)
{
    __shared__ float t8s[169 * 8];
    const int wi = blockIdx.x / HEADS, h = blockIdx.x % HEADS;
    for (int i = threadIdx.x; i < 169 * 8; i += blockDim.x)
        t8s[i] = g_t8[i];
    __syncthreads();
    const float* mp = mask + (size_t)wi * NN2;
    float* o = g_bm + (size_t)blockIdx.x * BMPAD;
    for (int i = threadIdx.x; i < BMPAD; i += blockDim.x) {
        if (i < NN2) {
            const float bv = t8s[idx[i] * 8 + h];
            o[i] = 16.f / (1.f + __expf(-bv)) + mp[i];
        } else {
            o[i] = 0.f;
        }
    }
}

// ---------------------------------------------------------------------------
// 2-stage cp.async tf32 GEMM (round-6 pipeline, operands pre-rounded in gmem
// so fragment loads are plain LDS). BM=128, BN=128, BK=16, 256 threads.
// ---------------------------------------------------------------------------
#define GEMM_PIPE(XPTR, WPTR)                                                     \
    __shared__ float As[2][128][20];                                              \
    __shared__ float Bs[2][128][20];                                              \
    const int tid = threadIdx.x;                                                  \
    const int lane = tid & 31, wid = tid >> 5;                                    \
    const int g = lane >> 2, tg = lane & 3;                                       \
    const int wm = (wid & 1) * 64, wn = (wid >> 1) * 32;                          \
    const int m0 = blockIdx.y * 128, n0 = blockIdx.x * 128;                       \
    const int lrow = tid >> 2, lcol = (tid & 3) * 4;                              \
    const float* gA0 = (XPTR) + (size_t)(m0 + lrow) * 256 + lcol;                 \
    const float* gA1 = gA0 + (size_t)64 * 256;                                    \
    const float* gB0 = (WPTR) + (size_t)(n0 + lrow) * 256 + lcol;                 \
    const float* gB1 = gB0 + (size_t)64 * 256;                                    \
    const unsigned sA = (unsigned)__cvta_generic_to_shared(&As[0][lrow][lcol]);   \
    const unsigned sB = (unsigned)__cvta_generic_to_shared(&Bs[0][lrow][lcol]);   \
    const unsigned STG = 128 * 20 * 4;                                            \
    const unsigned HLF = 64 * 20 * 4;                                             \
    float acc[4][4][4];                                                           \
    _Pragma("unroll") for (int i = 0; i < 4; ++i)                                 \
    _Pragma("unroll") for (int j = 0; j < 4; ++j)                                 \
    _Pragma("unroll") for (int r = 0; r < 4; ++r) acc[i][j][r] = 0.f;             \
    CPA16(sA,       gA0);                                                         \
    CPA16(sA + HLF, gA1);                                                         \
    CPA16(sB,       gB0);                                                         \
    CPA16(sB + HLF, gB1);                                                         \
    asm volatile("cp.async.commit_group;");                                       \
    for (int kb = 0; kb < 16; ++kb) {                                             \
        if (kb < 15) {                                                            \
            const int sNext = (kb + 1) & 1;                                       \
            const int kOff = (kb + 1) * 16;                                       \
            CPA16(sA + sNext * STG,       gA0 + kOff);                            \
            CPA16(sA + sNext * STG + HLF, gA1 + kOff);                            \
            CPA16(sB + sNext * STG,       gB0 + kOff);                            \
            CPA16(sB + sNext * STG + HLF, gB1 + kOff);                            \
            asm volatile("cp.async.commit_group;");                               \
            asm volatile("cp.async.wait_group 1;");                               \
        } else {                                                                  \
            asm volatile("cp.async.wait_group 0;");                               \
        }                                                                         \
        __syncthreads();                                                          \
        const int s = kb & 1;                                                     \
        _Pragma("unroll") for (int ks = 0; ks < 2; ++ks) {                        \
            const int kk = ks * 8;                                                \
            unsigned af[4][4], bf[4][2];                                          \
            _Pragma("unroll") for (int mi = 0; mi < 4; ++mi) {                    \
                const int r = wm + mi * 16 + g;                                   \
                af[mi][0] = __float_as_uint(As[s][r    ][kk + tg]);               \
                af[mi][1] = __float_as_uint(As[s][r + 8][kk + tg]);               \
                af[mi][2] = __float_as_uint(As[s][r    ][kk + tg + 4]);           \
                af[mi][3] = __float_as_uint(As[s][r + 8][kk + tg + 4]);           \
            }                                                                     \
            _Pragma("unroll") for (int ni = 0; ni < 4; ++ni) {                    \
                const int c = wn + ni * 8 + g;                                    \
                bf[ni][0] = __float_as_uint(Bs[s][c][kk + tg]);                   \
                bf[ni][1] = __float_as_uint(Bs[s][c][kk + tg + 4]);               \
            }                                                                     \
            _Pragma("unroll") for (int mi = 0; mi < 4; ++mi)                      \
            _Pragma("unroll") for (int ni = 0; ni < 4; ++ni)                      \
                mma_tf32(acc[mi][ni], af[mi], bf[ni]);                            \
        }                                                                         \
        __syncthreads();                                                          \
    }

__device__ __forceinline__ float qkvb(int o, const float* qb, const float* vb) {
    return (o < 256) ? qb[o] : ((o < 512) ? 0.f : vb[o - 512]);
}

__global__ __launch_bounds__(256) void mma_qkv(const float* __restrict__ qb,
                                               const float* __restrict__ vb)
{
    GEMM_PIPE(g_xr, g_wqr)
#pragma unroll
    for (int mi = 0; mi < 4; ++mi) {
        const int mA = m0 + wm + mi * 16 + g;
#pragma unroll
        for (int ni = 0; ni < 4; ++ni) {
            const int o = n0 + wn + ni * 8 + tg * 2;
            const float b0 = qkvb(o, qb, vb), b1 = qkvb(o + 1, qb, vb);
            float2 v0 = make_float2(acc[mi][ni][0] + b0, acc[mi][ni][1] + b1);
            float2 v1 = make_float2(acc[mi][ni][2] + b0, acc[mi][ni][3] + b1);
            *(float2*)&g_qkv[(size_t)mA * 768 + o]       = v0;
            *(float2*)&g_qkv[(size_t)(mA + 8) * 768 + o] = v1;
        }
    }
}

__global__ __launch_bounds__(256) void mma_proj(const float* __restrict__ pb,
                                                float* __restrict__ out)
{
    GEMM_PIPE(g_att, g_wpr)
#pragma unroll
    for (int mi = 0; mi < 4; ++mi) {
        const int mA = m0 + wm + mi * 16 + g;
#pragma unroll
        for (int ni = 0; ni < 4; ++ni) {
            const int o = n0 + wn + ni * 8 + tg * 2;
            const float b0 = pb[o], b1 = pb[o + 1];
            float2 v0 = make_float2(acc[mi][ni][0] + b0, acc[mi][ni][1] + b1);
            float2 v1 = make_float2(acc[mi][ni][2] + b0, acc[mi][ni][3] + b1);
            *(float2*)&out[(size_t)mA * 256 + o]       = v0;
            *(float2*)&out[(size_t)(mA + 8) * 256 + o] = v1;
        }
    }
}

// ---------------------------------------------------------------------------
// MMA attention (round-9 proven, 240us). One block per (b,h), 4 warps.
// ---------------------------------------------------------------------------
__global__ __launch_bounds__(128, 4) void attn_mma(const float* __restrict__ logit_scale,
                                                   int nW)
{
    __shared__ float2 qk2[2][64][37];   // [0]=q, [1]=k; (hi, lo)
    __shared__ float  vt[32][68];       // V^T, tf32-rounded
    __shared__ float  bms[BMPAD];       // bias+mask tile
    float* ps = (float*)qk2;            // [64][68] alias

    const int b = blockIdx.x, h = blockIdx.y;
    const int tid = threadIdx.x, w = tid >> 5, lane = tid & 31;
    const int g = lane >> 2, tg = lane & 3;
    const int wm = w * 16;
    const float scale = __expf(fminf(logit_scale[h], 4.605170185988092f)); // ln(100)

    // kick off bias+mask DMA first
    {
        const float* bmg = &g_bm[(size_t)((b % nW) * HEADS + h) * BMPAD];
        const unsigned sbm = (unsigned)__cvta_generic_to_shared(bms);
        for (int i = tid; i < BMPAD / 4; i += 128)
            CPA16(sbm + i * 16, bmg + i * 4);
        asm volatile("cp.async.commit_group;");
    }

    // zero token padding
    for (int i = tid; i < 2 * 15 * 37; i += 128) {
        const int s = i / (15 * 37), rem = i % (15 * 37);
        qk2[s][49 + rem / 37][rem % 37] = make_float2(0.f, 0.f);
    }
    for (int i = tid; i < 32 * 15; i += 128)
        vt[i / 15][49 + i % 15] = 0.f;

    // ---- prologue: 2 threads per token, 16 dims each ----
    {
        const int tokr = tid >> 1;
        const bool act = tokr < NTOK;
        const int tok = act ? tokr : NTOK - 1;
        const int hf = tid & 1;
        const float* rp = &g_qkv[(size_t)(b * NTOK + tok) * 768 + h * HD + hf * 16];
        float qv[16], kv[16], vv[16];
#pragma unroll
        for (int i = 0; i < 4; ++i) {
            const float4 q4 = *(const float4*)&rp[i * 4];
            const float4 k4 = *(const float4*)&rp[256 + i * 4];
            const float4 v4 = *(const float4*)&rp[512 + i * 4];
            qv[i*4+0]=q4.x; qv[i*4+1]=q4.y; qv[i*4+2]=q4.z; qv[i*4+3]=q4.w;
            kv[i*4+0]=k4.x; kv[i*4+1]=k4.y; kv[i*4+2]=k4.z; kv[i*4+3]=k4.w;
            vv[i*4+0]=v4.x; vv[i*4+1]=v4.y; vv[i*4+2]=v4.z; vv[i*4+3]=v4.w;
        }
        float sq = 0.f, sk = 0.f;
#pragma unroll
        for (int i = 0; i < 16; ++i) {
            sq = fmaf(qv[i], qv[i], sq);
            sk = fmaf(kv[i], kv[i], sk);
        }
        sq += __shfl_xor_sync(0xffffffffu, sq, 1);
        sk += __shfl_xor_sync(0xffffffffu, sk, 1);
        const float qs = scale / fmaxf(sqrtf(sq), 1e-12f);
        const float ks = 1.f / fmaxf(sqrtf(sk), 1e-12f);
        if (act) {
#pragma unroll
            for (int i = 0; i < 16; ++i) {
                const int d = hf * 16 + i;
                const float qn = qv[i] * qs;
                const float kn = kv[i] * ks;
                const float qhi = tf32r(qn), khi = tf32r(kn);
                qk2[0][tok][d] = make_float2(qhi, tf32r(qn - qhi));
                qk2[1][tok][d] = make_float2(khi, tf32r(kn - khi));
                vt[d][tok] = tf32r(vv[i]);
            }
        }
    }
    __syncthreads();

    // ---- QK^T (3xTF32), warp rows [wm, wm+16), all 64 cols ----
    float acc[8][4];
#pragma unroll
    for (int ni = 0; ni < 8; ++ni)
#pragma unroll
        for (int e = 0; e < 4; ++e) acc[ni][e] = 0.f;

#pragma unroll
    for (int ks = 0; ks < 4; ++ks) {
        const int kk = ks * 8;
        float2 aq[4];
        aq[0] = qk2[0][wm + g    ][kk + tg];
        aq[1] = qk2[0][wm + g + 8][kk + tg];
        aq[2] = qk2[0][wm + g    ][kk + tg + 4];
        aq[3] = qk2[0][wm + g + 8][kk + tg + 4];
        unsigned ah[4], al[4];
#pragma unroll
        for (int e = 0; e < 4; ++e) {
            ah[e] = __float_as_uint(aq[e].x);
            al[e] = __float_as_uint(aq[e].y);
        }
#pragma unroll
        for (int ni = 0; ni < 8; ++ni) {
            const int c = ni * 8 + g;
            const float2 b0 = qk2[1][c][kk + tg];
            const float2 b1 = qk2[1][c][kk + tg + 4];
            unsigned bh[2], bl[2];
            bh[0] = __float_as_uint(b0.x); bh[1] = __float_as_uint(b1.x);
            bl[0] = __float_as_uint(b0.y); bl[1] = __float_as_uint(b1.y);
            mma_tf32(acc[ni], ah, bh);
            mma_tf32(acc[ni], ah, bl);
            mma_tf32(acc[ni], al, bh);
        }
    }
    asm volatile("cp.async.wait_group 0;");   // bms resident
    __syncthreads();   // all warps done reading qk2; ps may overwrite it

    // ---- bias+mask add from smem, pad masking ----
    const int r0 = wm + g, r1 = wm + g + 8;
#pragma unroll
    for (int ni = 0; ni < 8; ++ni) {
        const int c0 = ni * 8 + tg * 2, c1 = c0 + 1;
        if (c0 < 49) { if (r0 < 49) acc[ni][0] += bms[r0 * 49 + c0];
                       if (r1 < 49) acc[ni][2] += bms[r1 * 49 + c0]; }
        else { acc[ni][0] = -1e30f; acc[ni][2] = -1e30f; }
        if (c1 < 49) { if (r0 < 49) acc[ni][1] += bms[r0 * 49 + c1];
                       if (r1 < 49) acc[ni][3] += bms[r1 * 49 + c1]; }
        else { acc[ni][1] = -1e30f; acc[ni][3] = -1e30f; }
    }

    // ---- softmax over 64 cols of rows r0, r1 ----
    float m0 = -1e30f, m1 = -1e30f;
#pragma unroll
    for (int ni = 0; ni < 8; ++ni) {
        m0 = fmaxf(m0, fmaxf(acc[ni][0], acc[ni][1]));
        m1 = fmaxf(m1, fmaxf(acc[ni][2], acc[ni][3]));
    }
    m0 = fmaxf(m0, __shfl_xor_sync(0xffffffffu, m0, 1));
    m0 = fmaxf(m0, __shfl_xor_sync(0xffffffffu, m0, 2));
    m1 = fmaxf(m1, __shfl_xor_sync(0xffffffffu, m1, 1));
    m1 = fmaxf(m1, __shfl_xor_sync(0xffffffffu, m1, 2));
    float s0 = 0.f, s1 = 0.f;
#pragma unroll
    for (int ni = 0; ni < 8; ++ni) {
        acc[ni][0] = __expf(acc[ni][0] - m0); s0 += acc[ni][0];
        acc[ni][1] = __expf(acc[ni][1] - m0); s0 += acc[ni][1];
        acc[ni][2] = __expf(acc[ni][2] - m1); s1 += acc[ni][2];
        acc[ni][3] = __expf(acc[ni][3] - m1); s1 += acc[ni][3];
    }
    s0 += __shfl_xor_sync(0xffffffffu, s0, 1);
    s0 += __shfl_xor_sync(0xffffffffu, s0, 2);
    s1 += __shfl_xor_sync(0xffffffffu, s1, 1);
    s1 += __shfl_xor_sync(0xffffffffu, s1, 2);
    const float i0 = 1.f / s0, i1 = 1.f / s1;
#pragma unroll
    for (int ni = 0; ni < 8; ++ni) {
        const int c0 = ni * 8 + tg * 2;
        ps[r0 * 68 + c0]     = tf32r(acc[ni][0] * i0);
        ps[r0 * 68 + c0 + 1] = tf32r(acc[ni][1] * i0);
        ps[r1 * 68 + c0]     = tf32r(acc[ni][2] * i1);
        ps[r1 * 68 + c0 + 1] = tf32r(acc[ni][3] * i1);
    }
    __syncwarp();   // ps rows [wm,wm+16) written & read only by this warp

    // ---- AV: out[16 x 32] = P[16 x 64] @ V[64 x 32] ----
    float oacc[4][4];
#pragma unroll
    for (int ni = 0; ni < 4; ++ni)
#pragma unroll
        for (int e = 0; e < 4; ++e) oacc[ni][e] = 0.f;

#pragma unroll
    for (int ks = 0; ks < 8; ++ks) {
        const int kk = ks * 8;
        unsigned a[4];
        a[0] = __float_as_uint(ps[(wm + g    ) * 68 + kk + tg]);
        a[1] = __float_as_uint(ps[(wm + g + 8) * 68 + kk + tg]);
        a[2] = __float_as_uint(ps[(wm + g    ) * 68 + kk + tg + 4]);
        a[3] = __float_as_uint(ps[(wm + g + 8) * 68 + kk + tg + 4]);
#pragma unroll
        for (int ni = 0; ni < 4; ++ni) {
            const int c = ni * 8 + g;
            unsigned bb[2];
            bb[0] = __float_as_uint(vt[c][kk + tg]);
            bb[1] = __float_as_uint(vt[c][kk + tg + 4]);
            mma_tf32(oacc[ni], a, bb);
        }
    }

    // tf32-rounded store (identical numerics to proj rounding it on load)
    if (r0 < 49) {
        float* op = &g_att[(size_t)(b * NTOK + r0) * CDIM + h * HD];
#pragma unroll
        for (int ni = 0; ni < 4; ++ni)
            *(float2*)&op[ni * 8 + tg * 2] =
                make_float2(tf32r(oacc[ni][0]), tf32r(oacc[ni][1]));
    }
    if (r1 < 49) {
        float* op = &g_att[(size_t)(b * NTOK + r1) * CDIM + h * HD];
#pragma unroll
        for (int ni = 0; ni < 4; ++ni)
            *(float2*)&op[ni * 8 + tg * 2] =
                make_float2(tf32r(oacc[ni][2]), tf32r(oacc[ni][3]));
    }
}

// ---------------------------------------------------------------------------
extern "C" void kernel_launch(void* const* d_in, const int* in_sizes, int n_in,
                              void* d_out, int out_size)
{
    const float* x        = (const float*)d_in[0];
    const float* mask     = (const float*)d_in[1];
    const float* qkv_w    = (const float*)d_in[2];
    const float* q_bias   = (const float*)d_in[3];
    const float* v_bias   = (const float*)d_in[4];
    const float* logit_sc = (const float*)d_in[5];
    const float* cpb_w1   = (const float*)d_in[6];
    const float* cpb_b1   = (const float*)d_in[7];
    const float* cpb_w2   = (const float*)d_in[8];
    const float* proj_w   = (const float*)d_in[9];
    const float* proj_b   = (const float*)d_in[10];
    const float* table    = (const float*)d_in[11];
    const int*   rel_idx  = (const int*)d_in[12];

    const int B  = in_sizes[0] / (NTOK * CDIM);      // 2048
    const int nW = in_sizes[1] / NN2;                // 64
    const int M  = B * NTOK;                         // 100352

    round_x_kernel<<<2048, 256>>>(x, M * CDIM / 4);
    round_w_kernel<<<256, 256>>>(qkv_w, proj_w);
    mma_qkv<<<dim3(768 / 128, M / 128), 256>>>(q_bias, v_bias);
    cpb_kernel<<<169, 256>>>(table, cpb_w1, cpb_b1, cpb_w2);
    bm_kernel<<<nW * HEADS, 256>>>(mask, rel_idx);
    attn_mma<<<dim3(B, HEADS), 128>>>(logit_sc, nW);
    mma_proj<<<dim3(256 / 128, M / 128), 256>>>(proj_b, (float*)d_out);
}

// round 12
// speedup vs baseline: 1.4354x; 1.0290x over previous
#include <cuda_runtime.h>
#include <math.h>

#define NTOK   49
#define CDIM   256
#define HEADS  8
#define HD     32
#define BMAX   2048
#define NN2    2401   // 49*49
#define BMPAD  2404   // NN2 padded so each row is 16B-aligned
#define NWMAX  64
#define MMAX   (BMAX * NTOK)
#define SPAD   24     // smem row pad (floats): conflict-free LDS.64 fragments

// Scratch (allocation-free: __device__ globals)
// g_xr / g_wqr / g_wpr / g_att use the within-8 permutation p=(k&3)*2+(k>>2)
__device__ float g_qkv[MMAX * 768];             // [M][768] natural layout
__device__ float g_att[MMAX * CDIM];            // [M][256] PERMUTED + tf32
__device__ float g_xr[MMAX * CDIM];             // PERMUTED + tf32 x
__device__ float g_wqr[768 * 256];              // PERMUTED + tf32 qkv_w
__device__ float g_wpr[256 * 256];              // PERMUTED + tf32 proj_w
__device__ float g_t8[169 * 8];                 // raw CPB MLP output [r][h]
__device__ float g_bm[NWMAX * HEADS * BMPAD];   // 16*sigmoid(bias) + mask

__device__ __forceinline__ float tf32r(float x) {
    unsigned u;
    asm("cvt.rna.tf32.f32 %0, %1;" : "=r"(u) : "f"(x));
    return __uint_as_float(u);
}

__device__ __forceinline__ void mma_tf32(float* c, const unsigned* a, const unsigned* b) {
    asm volatile(
        "mma.sync.aligned.m16n8k8.row.col.f32.tf32.tf32.f32 "
        "{%0,%1,%2,%3}, {%4,%5,%6,%7}, {%8,%9}, {%0,%1,%2,%3};"
        : "+f"(c[0]), "+f"(c[1]), "+f"(c[2]), "+f"(c[3])
        : "r"(a[0]), "r"(a[1]), "r"(a[2]), "r"(a[3]), "r"(b[0]), "r"(b[1]));
}

#define CPA16(dst_u32, src_ptr) \
    asm volatile("cp.async.cg.shared.global [%0], [%1], 16;" :: "r"(dst_u32), "l"(src_ptr))

// interleave two float4 k-groups (lo = k0..3, hi = k4..7) into permuted order
__device__ __forceinline__ void perm_store8(float* dst, float4 lo, float4 hi) {
    float4 o0 = make_float4(tf32r(lo.x), tf32r(hi.x), tf32r(lo.y), tf32r(hi.y));
    float4 o1 = make_float4(tf32r(lo.z), tf32r(hi.z), tf32r(lo.w), tf32r(hi.w));
    ((float4*)dst)[0] = o0;
    ((float4*)dst)[1] = o1;
}

// ---------------------------------------------------------------------------
// tf32 pre-round + permute passes
// ---------------------------------------------------------------------------
__global__ void round_x_kernel(const float* __restrict__ x, int n8)
{
    const int stride = gridDim.x * blockDim.x;
    for (int i = blockIdx.x * blockDim.x + threadIdx.x; i < n8; i += stride) {
        const float4 lo = ((const float4*)x)[2 * i];
        const float4 hi = ((const float4*)x)[2 * i + 1];
        perm_store8(&g_xr[8 * (size_t)i], lo, hi);
    }
}

__global__ void round_w_kernel(const float* __restrict__ qkv_w,
                               const float* __restrict__ proj_w)
{
    const int stride = gridDim.x * blockDim.x;
    const int nq = 768 * 256 / 8, np = 256 * 256 / 8;
    for (int i = blockIdx.x * blockDim.x + threadIdx.x; i < nq + np; i += stride) {
        if (i < nq) {
            const float4 lo = ((const float4*)qkv_w)[2 * i];
            const float4 hi = ((const float4*)qkv_w)[2 * i + 1];
            perm_store8(&g_wqr[8 * (size_t)i], lo, hi);
        } else {
            const int j = i - nq;
            const float4 lo = ((const float4*)proj_w)[2 * j];
            const float4 hi = ((const float4*)proj_w)[2 * j + 1];
            perm_store8(&g_wpr[8 * (size_t)j], lo, hi);
        }
    }
}

// ---------------------------------------------------------------------------
// CPB MLP, parallel: one warp per (row r, head hh). 169 blocks x 8 warps.
// ---------------------------------------------------------------------------
__global__ void cpb_kernel(const float* __restrict__ table,
                           const float* __restrict__ w1,
                           const float* __restrict__ b1,
                           const float* __restrict__ w2)
{
    const int r = blockIdx.x;                 // 0..168
    const int hh = threadIdx.x >> 5;          // 0..7
    const int lane = threadIdx.x & 31;
    const float t0 = table[r * 2 + 0];
    const float t1 = table[r * 2 + 1];
    float s = 0.f;
#pragma unroll
    for (int it = 0; it < 16; ++it) {
        const int j = lane + it * 32;
        float hv = fmaf(t0, w1[j * 2 + 0], fmaf(t1, w1[j * 2 + 1], b1[j]));
        hv = fmaxf(hv, 0.f);
        s = fmaf(hv, w2[hh * 512 + j], s);
    }
#pragma unroll
    for (int o = 16; o > 0; o >>= 1)
        s += __shfl_xor_sync(0xffffffffu, s, o);
    if (lane == 0) g_t8[r * 8 + hh] = s;
}

// g_bm[wi*H+h][ij] = 16*sigmoid(g_t8[idx[ij]][h]) + mask[wi][ij]
__global__ void bm_kernel(const float* __restrict__ mask,
                          const int* __restrict__ idx)
{
    __shared__ float t8s[169 * 8];
    const int wi = blockIdx.x / HEADS, h = blockIdx.x % HEADS;
    for (int i = threadIdx.x; i < 169 * 8; i += blockDim.x)
        t8s[i] = g_t8[i];
    __syncthreads();
    const float* mp = mask + (size_t)wi * NN2;
    float* o = g_bm + (size_t)blockIdx.x * BMPAD;
    for (int i = threadIdx.x; i < BMPAD; i += blockDim.x) {
        if (i < NN2) {
            const float bv = t8s[idx[i] * 8 + h];
            o[i] = 16.f / (1.f + __expf(-bv)) + mp[i];
        } else {
            o[i] = 0.f;
        }
    }
}

// ---------------------------------------------------------------------------
// 2-stage cp.async tf32 GEMM: operands pre-rounded AND permuted in gmem, so
// every fragment load is one conflict-free LDS.64. BM=128,BN=128,BK=16.
// ---------------------------------------------------------------------------
#define GEMM_PIPE(XPTR, WPTR)                                                     \
    __shared__ float As[2][128][SPAD];                                            \
    __shared__ float Bs[2][128][SPAD];                                            \
    const int tid = threadIdx.x;                                                  \
    const int lane = tid & 31, wid = tid >> 5;                                    \
    const int g = lane >> 2, tg = lane & 3;                                       \
    const int wm = (wid & 1) * 64, wn = (wid >> 1) * 32;                          \
    const int m0 = blockIdx.y * 128, n0 = blockIdx.x * 128;                       \
    const int lrow = tid >> 2, lcol = (tid & 3) * 4;                              \
    const float* gA0 = (XPTR) + (size_t)(m0 + lrow) * 256 + lcol;                 \
    const float* gA1 = gA0 + (size_t)64 * 256;                                    \
    const float* gB0 = (WPTR) + (size_t)(n0 + lrow) * 256 + lcol;                 \
    const float* gB1 = gB0 + (size_t)64 * 256;                                    \
    const unsigned sA = (unsigned)__cvta_generic_to_shared(&As[0][lrow][lcol]);   \
    const unsigned sB = (unsigned)__cvta_generic_to_shared(&Bs[0][lrow][lcol]);   \
    const unsigned STG = 128 * SPAD * 4;                                          \
    const unsigned HLF = 64 * SPAD * 4;                                           \
    float acc[4][4][4];                                                           \
    _Pragma("unroll") for (int i = 0; i < 4; ++i)                                 \
    _Pragma("unroll") for (int j = 0; j < 4; ++j)                                 \
    _Pragma("unroll") for (int r = 0; r < 4; ++r) acc[i][j][r] = 0.f;             \
    CPA16(sA,       gA0);                                                         \
    CPA16(sA + HLF, gA1);                                                         \
    CPA16(sB,       gB0);                                                         \
    CPA16(sB + HLF, gB1);                                                         \
    asm volatile("cp.async.commit_group;");                                       \
    for (int kb = 0; kb < 16; ++kb) {                                             \
        if (kb < 15) {                                                            \
            const int sNext = (kb + 1) & 1;                                       \
            const int kOff = (kb + 1) * 16;                                       \
            CPA16(sA + sNext * STG,       gA0 + kOff);                            \
            CPA16(sA + sNext * STG + HLF, gA1 + kOff);                            \
            CPA16(sB + sNext * STG,       gB0 + kOff);                            \
            CPA16(sB + sNext * STG + HLF, gB1 + kOff);                            \
            asm volatile("cp.async.commit_group;");                               \
            asm volatile("cp.async.wait_group 1;");                               \
        } else {                                                                  \
            asm volatile("cp.async.wait_group 0;");                               \
        }                                                                         \
        __syncthreads();                                                          \
        const int s = kb & 1;                                                     \
        _Pragma("unroll") for (int ks = 0; ks < 2; ++ks) {                        \
            const int kk = ks * 8;                                                \
            unsigned af[4][4], bf[4][2];                                          \
            _Pragma("unroll") for (int mi = 0; mi < 4; ++mi) {                    \
                const int r = wm + mi * 16 + g;                                   \
                const float2 aA = *(const float2*)&As[s][r    ][kk + tg * 2];     \
                const float2 aB = *(const float2*)&As[s][r + 8][kk + tg * 2];     \
                af[mi][0] = __float_as_uint(aA.x);                                \
                af[mi][1] = __float_as_uint(aB.x);                                \
                af[mi][2] = __float_as_uint(aA.y);                                \
                af[mi][3] = __float_as_uint(aB.y);                                \
            }                                                                     \
            _Pragma("unroll") for (int ni = 0; ni < 4; ++ni) {                    \
                const int c = wn + ni * 8 + g;                                    \
                const float2 bB = *(const float2*)&Bs[s][c][kk + tg * 2];         \
                bf[ni][0] = __float_as_uint(bB.x);                                \
                bf[ni][1] = __float_as_uint(bB.y);                                \
            }                                                                     \
            _Pragma("unroll") for (int mi = 0; mi < 4; ++mi)                      \
            _Pragma("unroll") for (int ni = 0; ni < 4; ++ni)                      \
                mma_tf32(acc[mi][ni], af[mi], bf[ni]);                            \
        }                                                                         \
        __syncthreads();                                                          \
    }

__device__ __forceinline__ float qkvb(int o, const float* qb, const float* vb) {
    return (o < 256) ? qb[o] : ((o < 512) ? 0.f : vb[o - 512]);
}

__global__ __launch_bounds__(256) void mma_qkv(const float* __restrict__ qb,
                                               const float* __restrict__ vb)
{
    GEMM_PIPE(g_xr, g_wqr)
#pragma unroll
    for (int mi = 0; mi < 4; ++mi) {
        const int mA = m0 + wm + mi * 16 + g;
#pragma unroll
        for (int ni = 0; ni < 4; ++ni) {
            const int o = n0 + wn + ni * 8 + tg * 2;
            const float b0 = qkvb(o, qb, vb), b1 = qkvb(o + 1, qb, vb);
            float2 v0 = make_float2(acc[mi][ni][0] + b0, acc[mi][ni][1] + b1);
            float2 v1 = make_float2(acc[mi][ni][2] + b0, acc[mi][ni][3] + b1);
            *(float2*)&g_qkv[(size_t)mA * 768 + o]       = v0;
            *(float2*)&g_qkv[(size_t)(mA + 8) * 768 + o] = v1;
        }
    }
}

__global__ __launch_bounds__(256) void mma_proj(const float* __restrict__ pb,
                                                float* __restrict__ out)
{
    GEMM_PIPE(g_att, g_wpr)
#pragma unroll
    for (int mi = 0; mi < 4; ++mi) {
        const int mA = m0 + wm + mi * 16 + g;
#pragma unroll
        for (int ni = 0; ni < 4; ++ni) {
            const int o = n0 + wn + ni * 8 + tg * 2;
            const float b0 = pb[o], b1 = pb[o + 1];
            float2 v0 = make_float2(acc[mi][ni][0] + b0, acc[mi][ni][1] + b1);
            float2 v1 = make_float2(acc[mi][ni][2] + b0, acc[mi][ni][3] + b1);
            *(float2*)&out[(size_t)mA * 256 + o]       = v0;
            *(float2*)&out[(size_t)(mA + 8) * 256 + o] = v1;
        }
    }
}

// ---------------------------------------------------------------------------
// MMA attention. One block per (b,h), 4 warps. Epilogue stores tf32-rounded
// output to g_att in the PERMUTED layout proj expects.
// ---------------------------------------------------------------------------
__global__ __launch_bounds__(128, 4) void attn_mma(const float* __restrict__ logit_scale,
                                                   int nW)
{
    __shared__ float2 qk2[2][64][37];   // [0]=q, [1]=k; (hi, lo)
    __shared__ float  vt[32][68];       // V^T, tf32-rounded
    __shared__ float  bms[BMPAD];       // bias+mask tile
    float* ps = (float*)qk2;            // [64][68] alias

    const int b = blockIdx.x, h = blockIdx.y;
    const int tid = threadIdx.x, w = tid >> 5, lane = tid & 31;
    const int g = lane >> 2, tg = lane & 3;
    const int wm = w * 16;
    const float scale = __expf(fminf(logit_scale[h], 4.605170185988092f)); // ln(100)

    // kick off bias+mask DMA first
    {
        const float* bmg = &g_bm[(size_t)((b % nW) * HEADS + h) * BMPAD];
        const unsigned sbm = (unsigned)__cvta_generic_to_shared(bms);
        for (int i = tid; i < BMPAD / 4; i += 128)
            CPA16(sbm + i * 16, bmg + i * 4);
        asm volatile("cp.async.commit_group;");
    }

    // zero token padding
    for (int i = tid; i < 2 * 15 * 37; i += 128) {
        const int s = i / (15 * 37), rem = i % (15 * 37);
        qk2[s][49 + rem / 37][rem % 37] = make_float2(0.f, 0.f);
    }
    for (int i = tid; i < 32 * 15; i += 128)
        vt[i / 15][49 + i % 15] = 0.f;

    // ---- prologue: 2 threads per token, 16 dims each ----
    {
        const int tokr = tid >> 1;
        const bool act = tokr < NTOK;
        const int tok = act ? tokr : NTOK - 1;
        const int hf = tid & 1;
        const float* rp = &g_qkv[(size_t)(b * NTOK + tok) * 768 + h * HD + hf * 16];
        float qv[16], kv[16], vv[16];
#pragma unroll
        for (int i = 0; i < 4; ++i) {
            const float4 q4 = *(const float4*)&rp[i * 4];
            const float4 k4 = *(const float4*)&rp[256 + i * 4];
            const float4 v4 = *(const float4*)&rp[512 + i * 4];
            qv[i*4+0]=q4.x; qv[i*4+1]=q4.y; qv[i*4+2]=q4.z; qv[i*4+3]=q4.w;
            kv[i*4+0]=k4.x; kv[i*4+1]=k4.y; kv[i*4+2]=k4.z; kv[i*4+3]=k4.w;
            vv[i*4+0]=v4.x; vv[i*4+1]=v4.y; vv[i*4+2]=v4.z; vv[i*4+3]=v4.w;
        }
        float sq = 0.f, sk = 0.f;
#pragma unroll
        for (int i = 0; i < 16; ++i) {
            sq = fmaf(qv[i], qv[i], sq);
            sk = fmaf(kv[i], kv[i], sk);
        }
        sq += __shfl_xor_sync(0xffffffffu, sq, 1);
        sk += __shfl_xor_sync(0xffffffffu, sk, 1);
        const float qs = scale / fmaxf(sqrtf(sq), 1e-12f);
        const float ks = 1.f / fmaxf(sqrtf(sk), 1e-12f);
        if (act) {
#pragma unroll
            for (int i = 0; i < 16; ++i) {
                const int d = hf * 16 + i;
                const float qn = qv[i] * qs;
                const float kn = kv[i] * ks;
                const float qhi = tf32r(qn), khi = tf32r(kn);
                qk2[0][tok][d] = make_float2(qhi, tf32r(qn - qhi));
                qk2[1][tok][d] = make_float2(khi, tf32r(kn - khi));
                vt[d][tok] = tf32r(vv[i]);
            }
        }
    }
    __syncthreads();

    // ---- QK^T (3xTF32), warp rows [wm, wm+16), all 64 cols ----
    float acc[8][4];
#pragma unroll
    for (int ni = 0; ni < 8; ++ni)
#pragma unroll
        for (int e = 0; e < 4; ++e) acc[ni][e] = 0.f;

#pragma unroll
    for (int ks = 0; ks < 4; ++ks) {
        const int kk = ks * 8;
        float2 aq[4];
        aq[0] = qk2[0][wm + g    ][kk + tg];
        aq[1] = qk2[0][wm + g + 8][kk + tg];
        aq[2] = qk2[0][wm + g    ][kk + tg + 4];
        aq[3] = qk2[0][wm + g + 8][kk + tg + 4];
        unsigned ah[4], al[4];
#pragma unroll
        for (int e = 0; e < 4; ++e) {
            ah[e] = __float_as_uint(aq[e].x);
            al[e] = __float_as_uint(aq[e].y);
        }
#pragma unroll
        for (int ni = 0; ni < 8; ++ni) {
            const int c = ni * 8 + g;
            const float2 b0 = qk2[1][c][kk + tg];
            const float2 b1 = qk2[1][c][kk + tg + 4];
            unsigned bh[2], bl[2];
            bh[0] = __float_as_uint(b0.x); bh[1] = __float_as_uint(b1.x);
            bl[0] = __float_as_uint(b0.y); bl[1] = __float_as_uint(b1.y);
            mma_tf32(acc[ni], ah, bh);
            mma_tf32(acc[ni], ah, bl);
            mma_tf32(acc[ni], al, bh);
        }
    }
    asm volatile("cp.async.wait_group 0;");   // bms resident
    __syncthreads();   // all warps done reading qk2; ps may overwrite it

    // ---- bias+mask add from smem, pad masking ----
    const int r0 = wm + g, r1 = wm + g + 8;
#pragma unroll
    for (int ni = 0; ni < 8; ++ni) {
        const int c0 = ni * 8 + tg * 2, c1 = c0 + 1;
        if (c0 < 49) { if (r0 < 49) acc[ni][0] += bms[r0 * 49 + c0];
                       if (r1 < 49) acc[ni][2] += bms[r1 * 49 + c0]; }
        else { acc[ni][0] = -1e30f; acc[ni][2] = -1e30f; }
        if (c1 < 49) { if (r0 < 49) acc[ni][1] += bms[r0 * 49 + c1];
                       if (r1 < 49) acc[ni][3] += bms[r1 * 49 + c1]; }
        else { acc[ni][1] = -1e30f; acc[ni][3] = -1e30f; }
    }

    // ---- softmax over 64 cols of rows r0, r1 ----
    float m0 = -1e30f, m1 = -1e30f;
#pragma unroll
    for (int ni = 0; ni < 8; ++ni) {
        m0 = fmaxf(m0, fmaxf(acc[ni][0], acc[ni][1]));
        m1 = fmaxf(m1, fmaxf(acc[ni][2], acc[ni][3]));
    }
    m0 = fmaxf(m0, __shfl_xor_sync(0xffffffffu, m0, 1));
    m0 = fmaxf(m0, __shfl_xor_sync(0xffffffffu, m0, 2));
    m1 = fmaxf(m1, __shfl_xor_sync(0xffffffffu, m1, 1));
    m1 = fmaxf(m1, __shfl_xor_sync(0xffffffffu, m1, 2));
    float s0 = 0.f, s1 = 0.f;
#pragma unroll
    for (int ni = 0; ni < 8; ++ni) {
        acc[ni][0] = __expf(acc[ni][0] - m0); s0 += acc[ni][0];
        acc[ni][1] = __expf(acc[ni][1] - m0); s0 += acc[ni][1];
        acc[ni][2] = __expf(acc[ni][2] - m1); s1 += acc[ni][2];
        acc[ni][3] = __expf(acc[ni][3] - m1); s1 += acc[ni][3];
    }
    s0 += __shfl_xor_sync(0xffffffffu, s0, 1);
    s0 += __shfl_xor_sync(0xffffffffu, s0, 2);
    s1 += __shfl_xor_sync(0xffffffffu, s1, 1);
    s1 += __shfl_xor_sync(0xffffffffu, s1, 2);
    const float i0 = 1.f / s0, i1 = 1.f / s1;
#pragma unroll
    for (int ni = 0; ni < 8; ++ni) {
        const int c0 = ni * 8 + tg * 2;
        ps[r0 * 68 + c0]     = tf32r(acc[ni][0] * i0);
        ps[r0 * 68 + c0 + 1] = tf32r(acc[ni][1] * i0);
        ps[r1 * 68 + c0]     = tf32r(acc[ni][2] * i1);
        ps[r1 * 68 + c0 + 1] = tf32r(acc[ni][3] * i1);
    }
    __syncwarp();   // ps rows [wm,wm+16) written & read only by this warp

    // ---- AV: out[16 x 32] = P[16 x 64] @ V[64 x 32] ----
    float oacc[4][4];
#pragma unroll
    for (int ni = 0; ni < 4; ++ni)
#pragma unroll
        for (int e = 0; e < 4; ++e) oacc[ni][e] = 0.f;

#pragma unroll
    for (int ks = 0; ks < 8; ++ks) {
        const int kk = ks * 8;
        unsigned a[4];
        a[0] = __float_as_uint(ps[(wm + g    ) * 68 + kk + tg]);
        a[1] = __float_as_uint(ps[(wm + g + 8) * 68 + kk + tg]);
        a[2] = __float_as_uint(ps[(wm + g    ) * 68 + kk + tg + 4]);
        a[3] = __float_as_uint(ps[(wm + g + 8) * 68 + kk + tg + 4]);
#pragma unroll
        for (int ni = 0; ni < 4; ++ni) {
            const int c = ni * 8 + g;
            unsigned bb[2];
            bb[0] = __float_as_uint(vt[c][kk + tg]);
            bb[1] = __float_as_uint(vt[c][kk + tg + 4]);
            mma_tf32(oacc[ni], a, bb);
        }
    }

    // permuted tf32 store: col j within its 8-group goes to p=(j&3)*2+(j>>2)
    const int j0 = tg * 2, j1 = tg * 2 + 1;
    const int p0 = (j0 & 3) * 2 + (j0 >> 2);
    const int p1 = (j1 & 3) * 2 + (j1 >> 2);
    if (r0 < 49) {
        float* op = &g_att[(size_t)(b * NTOK + r0) * CDIM + h * HD];
#pragma unroll
        for (int ni = 0; ni < 4; ++ni) {
            op[ni * 8 + p0] = tf32r(oacc[ni][0]);
            op[ni * 8 + p1] = tf32r(oacc[ni][1]);
        }
    }
    if (r1 < 49) {
        float* op = &g_att[(size_t)(b * NTOK + r1) * CDIM + h * HD];
#pragma unroll
        for (int ni = 0; ni < 4; ++ni) {
            op[ni * 8 + p0] = tf32r(oacc[ni][2]);
            op[ni * 8 + p1] = tf32r(oacc[ni][3]);
        }
    }
}

// ---------------------------------------------------------------------------
extern "C" void kernel_launch(void* const* d_in, const int* in_sizes, int n_in,
                              void* d_out, int out_size)
{
    const float* x        = (const float*)d_in[0];
    const float* mask     = (const float*)d_in[1];
    const float* qkv_w    = (const float*)d_in[2];
    const float* q_bias   = (const float*)d_in[3];
    const float* v_bias   = (const float*)d_in[4];
    const float* logit_sc = (const float*)d_in[5];
    const float* cpb_w1   = (const float*)d_in[6];
    const float* cpb_b1   = (const float*)d_in[7];
    const float* cpb_w2   = (const float*)d_in[8];
    const float* proj_w   = (const float*)d_in[9];
    const float* proj_b   = (const float*)d_in[10];
    const float* table    = (const float*)d_in[11];
    const int*   rel_idx  = (const int*)d_in[12];

    const int B  = in_sizes[0] / (NTOK * CDIM);      // 2048
    const int nW = in_sizes[1] / NN2;                // 64
    const int M  = B * NTOK;                         // 100352

    round_x_kernel<<<2048, 256>>>(x, M * CDIM / 8);
    round_w_kernel<<<128, 256>>>(qkv_w, proj_w);
    mma_qkv<<<dim3(768 / 128, M / 128), 256>>>(q_bias, v_bias);
    cpb_kernel<<<169, 256>>>(table, cpb_w1, cpb_b1, cpb_w2);
    bm_kernel<<<nW * HEADS, 256>>>(mask, rel_idx);
    attn_mma<<<dim3(B, HEADS), 128>>>(logit_sc, nW);
    mma_proj<<<dim3(256 / 128, M / 128), 256>>>(proj_b, (float*)d_out);
}

// round 13
// speedup vs baseline: 1.4516x; 1.0113x over previous
#include <cuda_runtime.h>
#include <math.h>

#define NTOK   49
#define CDIM   256
#define HEADS  8
#define HD     32
#define BMAX   2048
#define NN2    2401   // 49*49
#define BMPAD  2404   // NN2 padded so each row is 16B-aligned
#define NWMAX  64
#define MMAX   (BMAX * NTOK)
#define SPAD   24     // smem row pad (floats): conflict-free LDS.64 fragments

// Scratch (allocation-free: __device__ globals)
// g_xr / g_wqr / g_wpr / g_att use the within-8 permutation p=(k&3)*2+(k>>2)
__device__ float g_qkv[MMAX * 768];             // [M][768] natural layout
__device__ float g_att[MMAX * CDIM];            // [M][256] PERMUTED + tf32
__device__ float g_xr[MMAX * CDIM];             // PERMUTED + tf32 x
__device__ float g_wqr[768 * 256];              // PERMUTED + tf32 qkv_w
__device__ float g_wpr[256 * 256];              // PERMUTED + tf32 proj_w
__device__ float g_t8[169 * 8];                 // raw CPB MLP output [r][h]
__device__ float g_bm[NWMAX * HEADS * BMPAD];   // 16*sigmoid(bias) + mask

__device__ __forceinline__ float tf32r(float x) {
    unsigned u;
    asm("cvt.rna.tf32.f32 %0, %1;" : "=r"(u) : "f"(x));
    return __uint_as_float(u);
}

__device__ __forceinline__ void mma_tf32(float* c, const unsigned* a, const unsigned* b) {
    asm volatile(
        "mma.sync.aligned.m16n8k8.row.col.f32.tf32.tf32.f32 "
        "{%0,%1,%2,%3}, {%4,%5,%6,%7}, {%8,%9}, {%0,%1,%2,%3};"
        : "+f"(c[0]), "+f"(c[1]), "+f"(c[2]), "+f"(c[3])
        : "r"(a[0]), "r"(a[1]), "r"(a[2]), "r"(a[3]), "r"(b[0]), "r"(b[1]));
}

#define CPA16(dst_u32, src_ptr) \
    asm volatile("cp.async.cg.shared.global [%0], [%1], 16;" :: "r"(dst_u32), "l"(src_ptr))

// interleave two float4 k-groups (lo = k0..3, hi = k4..7) into permuted order
__device__ __forceinline__ void perm_store8(float* dst, float4 lo, float4 hi) {
    float4 o0 = make_float4(tf32r(lo.x), tf32r(hi.x), tf32r(lo.y), tf32r(hi.y));
    float4 o1 = make_float4(tf32r(lo.z), tf32r(hi.z), tf32r(lo.w), tf32r(hi.w));
    ((float4*)dst)[0] = o0;
    ((float4*)dst)[1] = o1;
}

// ---------------------------------------------------------------------------
// tf32 pre-round + permute passes
// ---------------------------------------------------------------------------
__global__ void round_x_kernel(const float* __restrict__ x, int n8)
{
    const int stride = gridDim.x * blockDim.x;
    for (int i = blockIdx.x * blockDim.x + threadIdx.x; i < n8; i += stride) {
        const float4 lo = ((const float4*)x)[2 * i];
        const float4 hi = ((const float4*)x)[2 * i + 1];
        perm_store8(&g_xr[8 * (size_t)i], lo, hi);
    }
}

__global__ void round_w_kernel(const float* __restrict__ qkv_w,
                               const float* __restrict__ proj_w)
{
    const int stride = gridDim.x * blockDim.x;
    const int nq = 768 * 256 / 8, np = 256 * 256 / 8;
    for (int i = blockIdx.x * blockDim.x + threadIdx.x; i < nq + np; i += stride) {
        if (i < nq) {
            const float4 lo = ((const float4*)qkv_w)[2 * i];
            const float4 hi = ((const float4*)qkv_w)[2 * i + 1];
            perm_store8(&g_wqr[8 * (size_t)i], lo, hi);
        } else {
            const int j = i - nq;
            const float4 lo = ((const float4*)proj_w)[2 * j];
            const float4 hi = ((const float4*)proj_w)[2 * j + 1];
            perm_store8(&g_wpr[8 * (size_t)j], lo, hi);
        }
    }
}

// ---------------------------------------------------------------------------
// CPB MLP, parallel: one warp per (row r, head hh). 169 blocks x 8 warps.
// ---------------------------------------------------------------------------
__global__ void cpb_kernel(const float* __restrict__ table,
                           const float* __restrict__ w1,
                           const float* __restrict__ b1,
                           const float* __restrict__ w2)
{
    const int r = blockIdx.x;                 // 0..168
    const int hh = threadIdx.x >> 5;          // 0..7
    const int lane = threadIdx.x & 31;
    const float t0 = table[r * 2 + 0];
    const float t1 = table[r * 2 + 1];
    float s = 0.f;
#pragma unroll
    for (int it = 0; it < 16; ++it) {
        const int j = lane + it * 32;
        float hv = fmaf(t0, w1[j * 2 + 0], fmaf(t1, w1[j * 2 + 1], b1[j]));
        hv = fmaxf(hv, 0.f);
        s = fmaf(hv, w2[hh * 512 + j], s);
    }
#pragma unroll
    for (int o = 16; o > 0; o >>= 1)
        s += __shfl_xor_sync(0xffffffffu, s, o);
    if (lane == 0) g_t8[r * 8 + hh] = s;
}

// g_bm[wi*H+h][ij] = 16*sigmoid(g_t8[idx[ij]][h]) + mask[wi][ij]
__global__ void bm_kernel(const float* __restrict__ mask,
                          const int* __restrict__ idx)
{
    __shared__ float t8s[169 * 8];
    const int wi = blockIdx.x / HEADS, h = blockIdx.x % HEADS;
    for (int i = threadIdx.x; i < 169 * 8; i += blockDim.x)
        t8s[i] = g_t8[i];
    __syncthreads();
    const float* mp = mask + (size_t)wi * NN2;
    float* o = g_bm + (size_t)blockIdx.x * BMPAD;
    for (int i = threadIdx.x; i < BMPAD; i += blockDim.x) {
        if (i < NN2) {
            const float bv = t8s[idx[i] * 8 + h];
            o[i] = 16.f / (1.f + __expf(-bv)) + mp[i];
        } else {
            o[i] = 0.f;
        }
    }
}

// ---------------------------------------------------------------------------
// 2-stage cp.async tf32 GEMM, 512 threads, warp tile 32x32 (2m x 4n frags).
// Operands pre-rounded + permuted in gmem -> fragment loads are LDS.64.
// Low register pressure -> 2 CTAs x 512 thr = 32 warps/SM.
// ---------------------------------------------------------------------------
#define GEMM_PIPE(XPTR, WPTR)                                                     \
    __shared__ float As[2][128][SPAD];                                            \
    __shared__ float Bs[2][128][SPAD];                                            \
    const int tid = threadIdx.x;                                                  \
    const int lane = tid & 31, wid = tid >> 5;                                    \
    const int g = lane >> 2, tg = lane & 3;                                       \
    const int wm = (wid & 3) * 32, wn = (wid >> 2) * 32;                          \
    const int m0 = blockIdx.y * 128, n0 = blockIdx.x * 128;                       \
    const int lrow = tid >> 2, lcol = (tid & 3) * 4;                              \
    const float* gA0 = (XPTR) + (size_t)(m0 + lrow) * 256 + lcol;                 \
    const float* gB0 = (WPTR) + (size_t)(n0 + lrow) * 256 + lcol;                 \
    const unsigned sA = (unsigned)__cvta_generic_to_shared(&As[0][lrow][lcol]);   \
    const unsigned sB = (unsigned)__cvta_generic_to_shared(&Bs[0][lrow][lcol]);   \
    const unsigned STG = 128 * SPAD * 4;                                          \
    float acc[2][4][4];                                                           \
    _Pragma("unroll") for (int i = 0; i < 2; ++i)                                 \
    _Pragma("unroll") for (int j = 0; j < 4; ++j)                                 \
    _Pragma("unroll") for (int r = 0; r < 4; ++r) acc[i][j][r] = 0.f;             \
    CPA16(sA, gA0);                                                               \
    CPA16(sB, gB0);                                                               \
    asm volatile("cp.async.commit_group;");                                       \
    for (int kb = 0; kb < 16; ++kb) {                                             \
        if (kb < 15) {                                                            \
            const int sNext = (kb + 1) & 1;                                       \
            const int kOff = (kb + 1) * 16;                                       \
            CPA16(sA + sNext * STG, gA0 + kOff);                                  \
            CPA16(sB + sNext * STG, gB0 + kOff);                                  \
            asm volatile("cp.async.commit_group;");                               \
            asm volatile("cp.async.wait_group 1;");                               \
        } else {                                                                  \
            asm volatile("cp.async.wait_group 0;");                               \
        }                                                                         \
        __syncthreads();                                                          \
        const int s = kb & 1;                                                     \
        _Pragma("unroll") for (int ks = 0; ks < 2; ++ks) {                        \
            const int kk = ks * 8;                                                \
            unsigned af[2][4], bf[4][2];                                          \
            _Pragma("unroll") for (int mi = 0; mi < 2; ++mi) {                    \
                const int r = wm + mi * 16 + g;                                   \
                const float2 aA = *(const float2*)&As[s][r    ][kk + tg * 2];     \
                const float2 aB = *(const float2*)&As[s][r + 8][kk + tg * 2];     \
                af[mi][0] = __float_as_uint(aA.x);                                \
                af[mi][1] = __float_as_uint(aB.x);                                \
                af[mi][2] = __float_as_uint(aA.y);                                \
                af[mi][3] = __float_as_uint(aB.y);                                \
            }                                                                     \
            _Pragma("unroll") for (int ni = 0; ni < 4; ++ni) {                    \
                const int c = wn + ni * 8 + g;                                    \
                const float2 bB = *(const float2*)&Bs[s][c][kk + tg * 2];         \
                bf[ni][0] = __float_as_uint(bB.x);                                \
                bf[ni][1] = __float_as_uint(bB.y);                                \
            }                                                                     \
            _Pragma("unroll") for (int mi = 0; mi < 2; ++mi)                      \
            _Pragma("unroll") for (int ni = 0; ni < 4; ++ni)                      \
                mma_tf32(acc[mi][ni], af[mi], bf[ni]);                            \
        }                                                                         \
        __syncthreads();                                                          \
    }

__device__ __forceinline__ float qkvb(int o, const float* qb, const float* vb) {
    return (o < 256) ? qb[o] : ((o < 512) ? 0.f : vb[o - 512]);
}

__global__ __launch_bounds__(512, 2) void mma_qkv(const float* __restrict__ qb,
                                                  const float* __restrict__ vb)
{
    GEMM_PIPE(g_xr, g_wqr)
#pragma unroll
    for (int mi = 0; mi < 2; ++mi) {
        const int mA = m0 + wm + mi * 16 + g;
#pragma unroll
        for (int ni = 0; ni < 4; ++ni) {
            const int o = n0 + wn + ni * 8 + tg * 2;
            const float b0 = qkvb(o, qb, vb), b1 = qkvb(o + 1, qb, vb);
            float2 v0 = make_float2(acc[mi][ni][0] + b0, acc[mi][ni][1] + b1);
            float2 v1 = make_float2(acc[mi][ni][2] + b0, acc[mi][ni][3] + b1);
            *(float2*)&g_qkv[(size_t)mA * 768 + o]       = v0;
            *(float2*)&g_qkv[(size_t)(mA + 8) * 768 + o] = v1;
        }
    }
}

__global__ __launch_bounds__(512, 2) void mma_proj(const float* __restrict__ pb,
                                                   float* __restrict__ out)
{
    GEMM_PIPE(g_att, g_wpr)
#pragma unroll
    for (int mi = 0; mi < 2; ++mi) {
        const int mA = m0 + wm + mi * 16 + g;
#pragma unroll
        for (int ni = 0; ni < 4; ++ni) {
            const int o = n0 + wn + ni * 8 + tg * 2;
            const float b0 = pb[o], b1 = pb[o + 1];
            float2 v0 = make_float2(acc[mi][ni][0] + b0, acc[mi][ni][1] + b1);
            float2 v1 = make_float2(acc[mi][ni][2] + b0, acc[mi][ni][3] + b1);
            *(float2*)&out[(size_t)mA * 256 + o]       = v0;
            *(float2*)&out[(size_t)(mA + 8) * 256 + o] = v1;
        }
    }
}

// ---------------------------------------------------------------------------
// MMA attention (round-12, unchanged). One block per (b,h), 4 warps.
// ---------------------------------------------------------------------------
__global__ __launch_bounds__(128, 4) void attn_mma(const float* __restrict__ logit_scale,
                                                   int nW)
{
    __shared__ float2 qk2[2][64][37];   // [0]=q, [1]=k; (hi, lo)
    __shared__ float  vt[32][68];       // V^T, tf32-rounded
    __shared__ float  bms[BMPAD];       // bias+mask tile
    float* ps = (float*)qk2;            // [64][68] alias

    const int b = blockIdx.x, h = blockIdx.y;
    const int tid = threadIdx.x, w = tid >> 5, lane = tid & 31;
    const int g = lane >> 2, tg = lane & 3;
    const int wm = w * 16;
    const float scale = __expf(fminf(logit_scale[h], 4.605170185988092f)); // ln(100)

    // kick off bias+mask DMA first
    {
        const float* bmg = &g_bm[(size_t)((b % nW) * HEADS + h) * BMPAD];
        const unsigned sbm = (unsigned)__cvta_generic_to_shared(bms);
        for (int i = tid; i < BMPAD / 4; i += 128)
            CPA16(sbm + i * 16, bmg + i * 4);
        asm volatile("cp.async.commit_group;");
    }

    // zero token padding
    for (int i = tid; i < 2 * 15 * 37; i += 128) {
        const int s = i / (15 * 37), rem = i % (15 * 37);
        qk2[s][49 + rem / 37][rem % 37] = make_float2(0.f, 0.f);
    }
    for (int i = tid; i < 32 * 15; i += 128)
        vt[i / 15][49 + i % 15] = 0.f;

    // ---- prologue: 2 threads per token, 16 dims each ----
    {
        const int tokr = tid >> 1;
        const bool act = tokr < NTOK;
        const int tok = act ? tokr : NTOK - 1;
        const int hf = tid & 1;
        const float* rp = &g_qkv[(size_t)(b * NTOK + tok) * 768 + h * HD + hf * 16];
        float qv[16], kv[16], vv[16];
#pragma unroll
        for (int i = 0; i < 4; ++i) {
            const float4 q4 = *(const float4*)&rp[i * 4];
            const float4 k4 = *(const float4*)&rp[256 + i * 4];
            const float4 v4 = *(const float4*)&rp[512 + i * 4];
            qv[i*4+0]=q4.x; qv[i*4+1]=q4.y; qv[i*4+2]=q4.z; qv[i*4+3]=q4.w;
            kv[i*4+0]=k4.x; kv[i*4+1]=k4.y; kv[i*4+2]=k4.z; kv[i*4+3]=k4.w;
            vv[i*4+0]=v4.x; vv[i*4+1]=v4.y; vv[i*4+2]=v4.z; vv[i*4+3]=v4.w;
        }
        float sq = 0.f, sk = 0.f;
#pragma unroll
        for (int i = 0; i < 16; ++i) {
            sq = fmaf(qv[i], qv[i], sq);
            sk = fmaf(kv[i], kv[i], sk);
        }
        sq += __shfl_xor_sync(0xffffffffu, sq, 1);
        sk += __shfl_xor_sync(0xffffffffu, sk, 1);
        const float qs = scale / fmaxf(sqrtf(sq), 1e-12f);
        const float ks = 1.f / fmaxf(sqrtf(sk), 1e-12f);
        if (act) {
#pragma unroll
            for (int i = 0; i < 16; ++i) {
                const int d = hf * 16 + i;
                const float qn = qv[i] * qs;
                const float kn = kv[i] * ks;
                const float qhi = tf32r(qn), khi = tf32r(kn);
                qk2[0][tok][d] = make_float2(qhi, tf32r(qn - qhi));
                qk2[1][tok][d] = make_float2(khi, tf32r(kn - khi));
                vt[d][tok] = tf32r(vv[i]);
            }
        }
    }
    __syncthreads();

    // ---- QK^T (3xTF32), warp rows [wm, wm+16), all 64 cols ----
    float acc[8][4];
#pragma unroll
    for (int ni = 0; ni < 8; ++ni)
#pragma unroll
        for (int e = 0; e < 4; ++e) acc[ni][e] = 0.f;

#pragma unroll
    for (int ks = 0; ks < 4; ++ks) {
        const int kk = ks * 8;
        float2 aq[4];
        aq[0] = qk2[0][wm + g    ][kk + tg];
        aq[1] = qk2[0][wm + g + 8][kk + tg];
        aq[2] = qk2[0][wm + g    ][kk + tg + 4];
        aq[3] = qk2[0][wm + g + 8][kk + tg + 4];
        unsigned ah[4], al[4];
#pragma unroll
        for (int e = 0; e < 4; ++e) {
            ah[e] = __float_as_uint(aq[e].x);
            al[e] = __float_as_uint(aq[e].y);
        }
#pragma unroll
        for (int ni = 0; ni < 8; ++ni) {
            const int c = ni * 8 + g;
            const float2 b0 = qk2[1][c][kk + tg];
            const float2 b1 = qk2[1][c][kk + tg + 4];
            unsigned bh[2], bl[2];
            bh[0] = __float_as_uint(b0.x); bh[1] = __float_as_uint(b1.x);
            bl[0] = __float_as_uint(b0.y); bl[1] = __float_as_uint(b1.y);
            mma_tf32(acc[ni], ah, bh);
            mma_tf32(acc[ni], ah, bl);
            mma_tf32(acc[ni], al, bh);
        }
    }
    asm volatile("cp.async.wait_group 0;");   // bms resident
    __syncthreads();   // all warps done reading qk2; ps may overwrite it

    // ---- bias+mask add from smem, pad masking ----
    const int r0 = wm + g, r1 = wm + g + 8;
#pragma unroll
    for (int ni = 0; ni < 8; ++ni) {
        const int c0 = ni * 8 + tg * 2, c1 = c0 + 1;
        if (c0 < 49) { if (r0 < 49) acc[ni][0] += bms[r0 * 49 + c0];
                       if (r1 < 49) acc[ni][2] += bms[r1 * 49 + c0]; }
        else { acc[ni][0] = -1e30f; acc[ni][2] = -1e30f; }
        if (c1 < 49) { if (r0 < 49) acc[ni][1] += bms[r0 * 49 + c1];
                       if (r1 < 49) acc[ni][3] += bms[r1 * 49 + c1]; }
        else { acc[ni][1] = -1e30f; acc[ni][3] = -1e30f; }
    }

    // ---- softmax over 64 cols of rows r0, r1 ----
    float m0 = -1e30f, m1 = -1e30f;
#pragma unroll
    for (int ni = 0; ni < 8; ++ni) {
        m0 = fmaxf(m0, fmaxf(acc[ni][0], acc[ni][1]));
        m1 = fmaxf(m1, fmaxf(acc[ni][2], acc[ni][3]));
    }
    m0 = fmaxf(m0, __shfl_xor_sync(0xffffffffu, m0, 1));
    m0 = fmaxf(m0, __shfl_xor_sync(0xffffffffu, m0, 2));
    m1 = fmaxf(m1, __shfl_xor_sync(0xffffffffu, m1, 1));
    m1 = fmaxf(m1, __shfl_xor_sync(0xffffffffu, m1, 2));
    float s0 = 0.f, s1 = 0.f;
#pragma unroll
    for (int ni = 0; ni < 8; ++ni) {
        acc[ni][0] = __expf(acc[ni][0] - m0); s0 += acc[ni][0];
        acc[ni][1] = __expf(acc[ni][1] - m0); s0 += acc[ni][1];
        acc[ni][2] = __expf(acc[ni][2] - m1); s1 += acc[ni][2];
        acc[ni][3] = __expf(acc[ni][3] - m1); s1 += acc[ni][3];
    }
    s0 += __shfl_xor_sync(0xffffffffu, s0, 1);
    s0 += __shfl_xor_sync(0xffffffffu, s0, 2);
    s1 += __shfl_xor_sync(0xffffffffu, s1, 1);
    s1 += __shfl_xor_sync(0xffffffffu, s1, 2);
    const float i0 = 1.f / s0, i1 = 1.f / s1;
#pragma unroll
    for (int ni = 0; ni < 8; ++ni) {
        const int c0 = ni * 8 + tg * 2;
        ps[r0 * 68 + c0]     = tf32r(acc[ni][0] * i0);
        ps[r0 * 68 + c0 + 1] = tf32r(acc[ni][1] * i0);
        ps[r1 * 68 + c0]     = tf32r(acc[ni][2] * i1);
        ps[r1 * 68 + c0 + 1] = tf32r(acc[ni][3] * i1);
    }
    __syncwarp();   // ps rows [wm,wm+16) written & read only by this warp

    // ---- AV: out[16 x 32] = P[16 x 64] @ V[64 x 32] ----
    float oacc[4][4];
#pragma unroll
    for (int ni = 0; ni < 4; ++ni)
#pragma unroll
        for (int e = 0; e < 4; ++e) oacc[ni][e] = 0.f;

#pragma unroll
    for (int ks = 0; ks < 8; ++ks) {
        const int kk = ks * 8;
        unsigned a[4];
        a[0] = __float_as_uint(ps[(wm + g    ) * 68 + kk + tg]);
        a[1] = __float_as_uint(ps[(wm + g + 8) * 68 + kk + tg]);
        a[2] = __float_as_uint(ps[(wm + g    ) * 68 + kk + tg + 4]);
        a[3] = __float_as_uint(ps[(wm + g + 8) * 68 + kk + tg + 4]);
#pragma unroll
        for (int ni = 0; ni < 4; ++ni) {
            const int c = ni * 8 + g;
            unsigned bb[2];
            bb[0] = __float_as_uint(vt[c][kk + tg]);
            bb[1] = __float_as_uint(vt[c][kk + tg + 4]);
            mma_tf32(oacc[ni], a, bb);
        }
    }

    // permuted tf32 store: col j within its 8-group goes to p=(j&3)*2+(j>>2)
    const int j0 = tg * 2, j1 = tg * 2 + 1;
    const int p0 = (j0 & 3) * 2 + (j0 >> 2);
    const int p1 = (j1 & 3) * 2 + (j1 >> 2);
    if (r0 < 49) {
        float* op = &g_att[(size_t)(b * NTOK + r0) * CDIM + h * HD];
#pragma unroll
        for (int ni = 0; ni < 4; ++ni) {
            op[ni * 8 + p0] = tf32r(oacc[ni][0]);
            op[ni * 8 + p1] = tf32r(oacc[ni][1]);
        }
    }
    if (r1 < 49) {
        float* op = &g_att[(size_t)(b * NTOK + r1) * CDIM + h * HD];
#pragma unroll
        for (int ni = 0; ni < 4; ++ni) {
            op[ni * 8 + p0] = tf32r(oacc[ni][2]);
            op[ni * 8 + p1] = tf32r(oacc[ni][3]);
        }
    }
}

// ---------------------------------------------------------------------------
extern "C" void kernel_launch(void* const* d_in, const int* in_sizes, int n_in,
                              void* d_out, int out_size)
{
    const float* x        = (const float*)d_in[0];
    const float* mask     = (const float*)d_in[1];
    const float* qkv_w    = (const float*)d_in[2];
    const float* q_bias   = (const float*)d_in[3];
    const float* v_bias   = (const float*)d_in[4];
    const float* logit_sc = (const float*)d_in[5];
    const float* cpb_w1   = (const float*)d_in[6];
    const float* cpb_b1   = (const float*)d_in[7];
    const float* cpb_w2   = (const float*)d_in[8];
    const float* proj_w   = (const float*)d_in[9];
    const float* proj_b   = (const float*)d_in[10];
    const float* table    = (const float*)d_in[11];
    const int*   rel_idx  = (const int*)d_in[12];

    const int B  = in_sizes[0] / (NTOK * CDIM);      // 2048
    const int nW = in_sizes[1] / NN2;                // 64
    const int M  = B * NTOK;                         // 100352

    round_x_kernel<<<2048, 256>>>(x, M * CDIM / 8);
    round_w_kernel<<<128, 256>>>(qkv_w, proj_w);
    mma_qkv<<<dim3(768 / 128, M / 128), 512>>>(q_bias, v_bias);
    cpb_kernel<<<169, 256>>>(table, cpb_w1, cpb_b1, cpb_w2);
    bm_kernel<<<nW * HEADS, 256>>>(mask, rel_idx);
    attn_mma<<<dim3(B, HEADS), 128>>>(logit_sc, nW);
    mma_proj<<<dim3(256 / 128, M / 128), 512>>>(proj_b, (float*)d_out);
}